// round 7
// baseline (speedup 1.0000x reference)
#include <cuda_runtime.h>
#include <cuda_bf16.h>
#include <cstdint>
#include <math.h>

// ---------------------------------------------------------------------------
// GraphSAGE 2-layer. CSR gather-mean (bf16 payload) + TF32 mma.sync GEMMs.
// Graph shape: prep -> fork{ xpart=x@Wr1+bl1 } || { hist->scan->fill->gather }
//              -> join -> h=relu(mean@Wl1+xpart) -> y2 -> gather_final.
// ---------------------------------------------------------------------------

#define N_MAX 100000
#define E_MAX 1600000

__device__ float    g_mean[(size_t)N_MAX * 128];
__device__ float    g_h   [(size_t)N_MAX * 128];
__device__ float    g_xp  [(size_t)N_MAX * 128];   // x@Wr1 + bl1
__device__ float    g_y2hi[(size_t)N_MAX * 64];
__device__ uint16_t g_xb  [(size_t)N_MAX * 128];   // bf16 bits
__device__ uint16_t g_y2b [(size_t)N_MAX * 64];    // bf16 bits
__device__ float    g_w1lt[128 * 128];             // Wl1^T  K-major, tf32-rounded
__device__ float    g_w1rt[128 * 128];             // Wr1^T
__device__ float    g_w2t [128 * 128];             // [Wl2|Wr2]^T
__device__ int      g_cnt[N_MAX];
__device__ int      g_cur[N_MAX];
__device__ int      g_rowptr[N_MAX];
__device__ int      g_eidx[E_MAX];
__device__ int      g_total;
__device__ int      g_is64;

// ---------------- helpers ----------------
__device__ __forceinline__ uint32_t f2tf32(float x) {
    uint32_t r;
    asm("cvt.rna.tf32.f32 %0, %1;" : "=r"(r) : "f"(x));
    return r;
}
__device__ __forceinline__ void mma_tf32(float (&c)[4], const uint32_t (&a)[4],
                                         const uint32_t (&b)[2]) {
    asm volatile(
        "mma.sync.aligned.m16n8k8.row.col.f32.tf32.tf32.f32 "
        "{%0,%1,%2,%3}, {%4,%5,%6,%7}, {%8,%9}, {%0,%1,%2,%3};"
        : "+f"(c[0]), "+f"(c[1]), "+f"(c[2]), "+f"(c[3])
        : "r"(a[0]), "r"(a[1]), "r"(a[2]), "r"(a[3]), "r"(b[0]), "r"(b[1]));
}
__device__ __forceinline__ float2 bf2_to_f2(uint32_t v) {
    __nv_bfloat162 b = *reinterpret_cast<__nv_bfloat162*>(&v);
    return __bfloat1622float2(b);
}
__device__ __forceinline__ uint32_t f2_to_bf2(float lo, float hi) {
    __nv_bfloat162 b = __floats2bfloat162_rn(lo, hi);
    return *reinterpret_cast<uint32_t*>(&b);
}
__device__ __forceinline__ uint32_t smem_u32(const void* p) {
    uint32_t a;
    asm("{ .reg .u64 t; cvta.to.shared.u64 t, %1; cvt.u32.u64 %0, t; }"
        : "=r"(a) : "l"(p));
    return a;
}
__device__ __forceinline__ void cp_async16(uint32_t smem, const void* g, int src_bytes) {
    asm volatile("cp.async.ca.shared.global [%0], [%1], 16, %2;"
                 :: "r"(smem), "l"(g), "r"(src_bytes) : "memory");
}
#define CP_COMMIT() asm volatile("cp.async.commit_group;" ::: "memory")
#define CP_WAIT0()  asm volatile("cp.async.wait_group 0;" ::: "memory")
#define CP_WAIT1()  asm volatile("cp.async.wait_group 1;" ::: "memory")

__device__ __forceinline__ int swz(int r, int k) {
    return (r << 5) + ((k & ~3) ^ ((r & 7) << 2)) + (k & 3);
}

// ---------------- CSR build ----------------
__device__ __forceinline__ int edge_at(const void* ei, long long idx, int is64) {
    if (is64) return (int)((const long long*)ei)[idx];
    return ((const int*)ei)[idx];
}
__global__ void hist_kernel(const void* __restrict__ ei, int* __restrict__ cnt, int ne) {
    int i = blockIdx.x * blockDim.x + threadIdx.x;
    int is64 = g_is64;
    if (i < ne) atomicAdd(&cnt[edge_at(ei, (long long)ne + i, is64)], 1);
}
// order-free scan: per-block Hillis + atomic ticket for block base.
__global__ void scan_kernel(const int* __restrict__ cnt, int* __restrict__ rowptr,
                            int* __restrict__ cur, int* __restrict__ total, int n) {
    __shared__ int sh[512];
    __shared__ int base_s;
    int tid = threadIdx.x;
    int i = blockIdx.x * 512 + tid;
    int v = (i < n) ? cnt[i] : 0;
    sh[tid] = v;
    __syncthreads();
    for (int off = 1; off < 512; off <<= 1) {
        int t = (tid >= off) ? sh[tid - off] : 0;
        __syncthreads();
        sh[tid] += t;
        __syncthreads();
    }
    if (tid == 511) base_s = atomicAdd(total, sh[511]);
    __syncthreads();
    int excl = sh[tid] - v + base_s;
    if (i < n) { rowptr[i] = excl; cur[i] = excl; }
}
__global__ void fill_kernel(const void* __restrict__ ei, int* __restrict__ cur,
                            int* __restrict__ eidx, int ne) {
    int i = blockIdx.x * blockDim.x + threadIdx.x;
    int is64 = g_is64;
    if (i < ne) {
        int s = edge_at(ei, i, is64);
        int d = edge_at(ei, (long long)ne + i, is64);
        eidx[atomicAdd(&cur[d], 1)] = s;
    }
}

// ---------------- fused prep ----------------
__global__ void prep_kernel(const float* __restrict__ x, uint16_t* __restrict__ xb,
                            const float* __restrict__ Wl1, const float* __restrict__ Wr1,
                            float* __restrict__ W1lt, float* __restrict__ W1rt,
                            const float* __restrict__ Wl2, const float* __restrict__ Wr2,
                            float* __restrict__ W2t,
                            int* __restrict__ cnt,
                            const int* __restrict__ ei, int n32, int n) {
    int i = blockIdx.x * blockDim.x + threadIdx.x;
    if (i < n32) {
        float4 v = __ldg((const float4*)x + i);
        uint2 o;
        o.x = f2_to_bf2(v.x, v.y);
        o.y = f2_to_bf2(v.z, v.w);
        *((uint2*)xb + i) = o;
        return;
    }
    int j = i - n32;
    if (j < 16384) {                          // W1lt
        int nn = j >> 7, k = j & 127;
        W1lt[j] = __uint_as_float(f2tf32(Wl1[k * 128 + nn]));
    } else if (j < 2 * 16384) {               // W1rt
        int jj = j - 16384;
        int nn = jj >> 7, k = jj & 127;
        W1rt[jj] = __uint_as_float(f2tf32(Wr1[k * 128 + nn]));
    } else if (j < 3 * 16384) {               // W2t
        int jj = j - 2 * 16384;
        int nn = jj >> 7, k = jj & 127;
        float v = (nn < 64) ? Wl2[k * 64 + nn] : Wr2[k * 64 + (nn - 64)];
        W2t[jj] = __uint_as_float(f2tf32(v));
    } else if (j < 3 * 16384 + n) {            // zero cnt
        cnt[j - 3 * 16384] = 0;
    } else if (j == 3 * 16384 + n) {           // detect + zero ticket
        int nz = 0;
        for (int q = 1; q < 256; q += 2) nz += (ei[q] != 0);
        g_is64 = (nz == 0) ? 1 : 0;
        g_total = 0;
    }
}

// ---------------- gathers (unroll-4; end = beg + cnt) ----------------
__global__ void gather_mean128_bf16(const uint16_t* __restrict__ featb,
                                    const int* __restrict__ rowptr,
                                    const int* __restrict__ cnt,
                                    const int* __restrict__ eidx,
                                    float* __restrict__ mean, int n) {
    int node = (blockIdx.x * blockDim.x + threadIdx.x) >> 5;
    if (node >= n) return;
    int lane = threadIdx.x & 31;
    int beg = __ldg(&rowptr[node]);
    int deg = __ldg(&cnt[node]);
    int end = beg + deg;
    float4 acc = make_float4(0.f, 0.f, 0.f, 0.f);
    const uint2* fb = (const uint2*)featb;
    int j = beg;
    for (; j + 3 < end; j += 4) {
        int s0 = __ldg(&eidx[j]),     s1 = __ldg(&eidx[j + 1]);
        int s2 = __ldg(&eidx[j + 2]), s3 = __ldg(&eidx[j + 3]);
        uint2 v0 = __ldg(&fb[(size_t)s0 * 32 + lane]);
        uint2 v1 = __ldg(&fb[(size_t)s1 * 32 + lane]);
        uint2 v2 = __ldg(&fb[(size_t)s2 * 32 + lane]);
        uint2 v3 = __ldg(&fb[(size_t)s3 * 32 + lane]);
        float2 a0 = bf2_to_f2(v0.x), a1 = bf2_to_f2(v0.y);
        float2 b0 = bf2_to_f2(v1.x), b1 = bf2_to_f2(v1.y);
        float2 c0 = bf2_to_f2(v2.x), c1 = bf2_to_f2(v2.y);
        float2 d0 = bf2_to_f2(v3.x), d1 = bf2_to_f2(v3.y);
        acc.x += (a0.x + b0.x) + (c0.x + d0.x);
        acc.y += (a0.y + b0.y) + (c0.y + d0.y);
        acc.z += (a1.x + b1.x) + (c1.x + d1.x);
        acc.w += (a1.y + b1.y) + (c1.y + d1.y);
    }
    for (; j < end; ++j) {
        int s0 = __ldg(&eidx[j]);
        uint2 v0 = __ldg(&fb[(size_t)s0 * 32 + lane]);
        float2 a0 = bf2_to_f2(v0.x), a1 = bf2_to_f2(v0.y);
        acc.x += a0.x; acc.y += a0.y; acc.z += a1.x; acc.w += a1.y;
    }
    float inv = 1.0f / fmaxf((float)deg, 1.0f);
    acc.x *= inv; acc.y *= inv; acc.z *= inv; acc.w *= inv;
    ((float4*)mean)[(size_t)node * 32 + lane] = acc;
}

__global__ void gather_final64(const uint16_t* __restrict__ y2b,
                               const float* __restrict__ y2hi,
                               const float* __restrict__ bl2,
                               const int* __restrict__ rowptr,
                               const int* __restrict__ cnt,
                               const int* __restrict__ eidx,
                               float* __restrict__ out, int n) {
    int node = (blockIdx.x * blockDim.x + threadIdx.x) >> 5;
    if (node >= n) return;
    int lane = threadIdx.x & 31;
    int beg = __ldg(&rowptr[node]);
    int deg = __ldg(&cnt[node]);
    int end = beg + deg;
    float2 acc = make_float2(0.f, 0.f);
    const uint32_t* fb = (const uint32_t*)y2b;
    int j = beg;
    for (; j + 3 < end; j += 4) {
        int s0 = __ldg(&eidx[j]),     s1 = __ldg(&eidx[j + 1]);
        int s2 = __ldg(&eidx[j + 2]), s3 = __ldg(&eidx[j + 3]);
        float2 v0 = bf2_to_f2(__ldg(&fb[(size_t)s0 * 32 + lane]));
        float2 v1 = bf2_to_f2(__ldg(&fb[(size_t)s1 * 32 + lane]));
        float2 v2 = bf2_to_f2(__ldg(&fb[(size_t)s2 * 32 + lane]));
        float2 v3 = bf2_to_f2(__ldg(&fb[(size_t)s3 * 32 + lane]));
        acc.x += (v0.x + v1.x) + (v2.x + v3.x);
        acc.y += (v0.y + v1.y) + (v2.y + v3.y);
    }
    for (; j < end; ++j) {
        int s0 = __ldg(&eidx[j]);
        float2 v0 = bf2_to_f2(__ldg(&fb[(size_t)s0 * 32 + lane]));
        acc.x += v0.x; acc.y += v0.y;
    }
    float inv = 1.0f / fmaxf((float)deg, 1.0f);
    float2 yh = *(const float2*)(y2hi + (size_t)node * 64 + lane * 2);
    float2 bb = *(const float2*)(bl2 + lane * 2);
    float2 o;
    o.x = 1.0f / (1.0f + __expf(-(acc.x * inv + yh.x + bb.x)));
    o.y = 1.0f / (1.0f + __expf(-(acc.y * inv + yh.y + bb.y)));
    *(float2*)(out + (size_t)node * 64 + lane * 2) = o;
}

// ---------------------------------------------------------------------------
// TF32 mma.sync GEMM, K=128, cp.async double-buffered, XOR-swizzled SMEM.
// C[128-tile,128] = A[*,128] @ Wt^T (Wt: [128,128] K-major, tf32-rounded).
// EPI 2: cols<64 -> bf16 outb[n,64]; cols>=64 -> f32 outhi[n,64]
// EPI 3: c + bias                        -> f32 out[n,128]
// EPI 4: relu(c + addv[row,col])         -> f32 out[n,128]
// ---------------------------------------------------------------------------
template<int EPI>
__global__ void __launch_bounds__(256, 2)
mma_gemm(const float* __restrict__ A0, const float* __restrict__ Wt,
         const float* __restrict__ bias, const float* __restrict__ addv,
         float* __restrict__ out, uint16_t* __restrict__ outb,
         float* __restrict__ outhi, int n)
{
    constexpr int NCHUNK = 4;
    extern __shared__ float smem[];
    const uint32_t* As = (const uint32_t*)smem;           // [2][4096]
    const uint32_t* Ws = (const uint32_t*)(smem + 8192);  // [2][4096]

    const int tid  = threadIdx.x;
    const int wid  = tid >> 5;
    const int lane = tid & 31;
    const int wm   = wid & 1;
    const int wn   = wid >> 1;
    const int g    = lane >> 2;
    const int tg   = lane & 3;
    const int row0 = blockIdx.x * 128;

    const uint32_t as_b = smem_u32(smem);
    const uint32_t ws_b = as_b + 8192 * 4;

    float c[4][4][4];
#pragma unroll
    for (int mi = 0; mi < 4; mi++)
#pragma unroll
        for (int ni = 0; ni < 4; ni++)
#pragma unroll
            for (int j = 0; j < 4; j++) c[mi][ni][j] = 0.f;

    auto prefetch = [&](int ch, int stage) {
        const int kcol = ch * 32;
        const uint32_t sofs = (uint32_t)stage << 14;
#pragma unroll
        for (int i = tid; i < 1024; i += 256) {
            int r = i >> 3, k4 = i & 7;
            uint32_t widx = (uint32_t)((r << 5) + ((k4 << 2) ^ ((r & 7) << 2)));
            int node = row0 + r;
            int ok = (node < n);
            const float* gA = A0 + (size_t)(ok ? node : 0) * 128 + kcol + (k4 << 2);
            cp_async16(as_b + sofs + widx * 4, gA, ok ? 16 : 0);
            const float* gW = Wt + (size_t)r * 128 + kcol + (k4 << 2);
            cp_async16(ws_b + sofs + widx * 4, gW, 16);
        }
        CP_COMMIT();
    };

    prefetch(0, 0);

#pragma unroll 1
    for (int ch = 0; ch < NCHUNK; ++ch) {
        const int stage = ch & 1;
        if (ch + 1 < NCHUNK) {
            prefetch(ch + 1, stage ^ 1);
            CP_WAIT1();
        } else {
            CP_WAIT0();
        }
        __syncthreads();

        const uint32_t* Ab = As + (stage << 12);
        const uint32_t* Wb = Ws + (stage << 12);

#pragma unroll
        for (int ks = 0; ks < 4; ++ks) {
            const int k0 = ks * 8;
            uint32_t a[4][4];
#pragma unroll
            for (int mi = 0; mi < 4; mi++) {
                int r0 = wm * 64 + mi * 16 + g;
                a[mi][0] = Ab[swz(r0,     k0 + tg)];
                a[mi][1] = Ab[swz(r0 + 8, k0 + tg)];
                a[mi][2] = Ab[swz(r0,     k0 + tg + 4)];
                a[mi][3] = Ab[swz(r0 + 8, k0 + tg + 4)];
            }
#pragma unroll
            for (int ni = 0; ni < 4; ni++) {
                int nb = wn * 32 + ni * 8 + g;
                uint32_t b[2];
                b[0] = Wb[swz(nb, k0 + tg)];
                b[1] = Wb[swz(nb, k0 + tg + 4)];
#pragma unroll
                for (int mi = 0; mi < 4; mi++)
                    mma_tf32(c[mi][ni], a[mi], b);
            }
        }
        __syncthreads();
    }

#pragma unroll
    for (int mi = 0; mi < 4; mi++) {
#pragma unroll
        for (int half = 0; half < 2; half++) {
            int row = row0 + wm * 64 + mi * 16 + g + half * 8;
            if (row < n) {
#pragma unroll
                for (int ni = 0; ni < 4; ni++) {
                    int col = wn * 32 + ni * 8 + tg * 2;
                    float v0 = c[mi][ni][half * 2 + 0];
                    float v1 = c[mi][ni][half * 2 + 1];
                    if (EPI == 3) {
                        v0 += __ldg(&bias[col]);
                        v1 += __ldg(&bias[col + 1]);
                        *(float2*)(out + (size_t)row * 128 + col) = make_float2(v0, v1);
                    } else if (EPI == 4) {
                        float2 ad = *(const float2*)(addv + (size_t)row * 128 + col);
                        v0 = fmaxf(v0 + ad.x, 0.f);
                        v1 = fmaxf(v1 + ad.y, 0.f);
                        *(float2*)(out + (size_t)row * 128 + col) = make_float2(v0, v1);
                    } else {    // EPI == 2
                        if (col < 64) {
                            *(uint32_t*)(outb + (size_t)row * 64 + col) = f2_to_bf2(v0, v1);
                        } else {
                            *(float2*)(outhi + (size_t)row * 64 + (col - 64)) =
                                make_float2(v0, v1);
                        }
                    }
                }
            }
        }
    }
}

// ---------------------------------------------------------------------------
extern "C" void kernel_launch(void* const* d_in, const int* in_sizes, int n_in,
                              void* d_out, int out_size) {
    const float* x   = (const float*)d_in[0];
    const void*  ei  = d_in[1];
    const float* Wl1 = (const float*)d_in[2];
    const float* bl1 = (const float*)d_in[3];
    const float* Wr1 = (const float*)d_in[4];
    const float* Wl2 = (const float*)d_in[5];
    const float* bl2 = (const float*)d_in[6];
    const float* Wr2 = (const float*)d_in[7];
    float* out = (float*)d_out;

    const int n  = in_sizes[0] / 128;   // 100000
    const int ne = in_sizes[1] / 2;     // 1600000

    float *mean, *h, *xp, *y2hi, *w1lt, *w1rt, *w2t;
    uint16_t *xb, *y2b;
    int *cnt, *cur, *rowptr, *eidx, *total;
    cudaGetSymbolAddress((void**)&mean,   g_mean);
    cudaGetSymbolAddress((void**)&h,      g_h);
    cudaGetSymbolAddress((void**)&xp,     g_xp);
    cudaGetSymbolAddress((void**)&y2hi,   g_y2hi);
    cudaGetSymbolAddress((void**)&xb,     g_xb);
    cudaGetSymbolAddress((void**)&y2b,    g_y2b);
    cudaGetSymbolAddress((void**)&w1lt,   g_w1lt);
    cudaGetSymbolAddress((void**)&w1rt,   g_w1rt);
    cudaGetSymbolAddress((void**)&w2t,    g_w2t);
    cudaGetSymbolAddress((void**)&cnt,    g_cnt);
    cudaGetSymbolAddress((void**)&cur,    g_cur);
    cudaGetSymbolAddress((void**)&rowptr, g_rowptr);
    cudaGetSymbolAddress((void**)&eidx,   g_eidx);
    cudaGetSymbolAddress((void**)&total,  g_total);

    cudaFuncSetAttribute(mma_gemm<2>, cudaFuncAttributeMaxDynamicSharedMemorySize, 65536);
    cudaFuncSetAttribute(mma_gemm<3>, cudaFuncAttributeMaxDynamicSharedMemorySize, 65536);
    cudaFuncSetAttribute(mma_gemm<4>, cudaFuncAttributeMaxDynamicSharedMemorySize, 65536);

    const int nscan = (n + 511) / 512;
    const int eblk  = (ne + 255) / 256;
    const int gblk  = (n + 7) / 8;
    const int mblk  = (n + 127) / 128;
    const int n32   = n * 32;
    const int pitems = n32 + 3 * 16384 + n + 1;
    const int pblk  = (pitems + 255) / 256;

    // Fork resources (created per call; host-side only, never device memory).
    cudaStream_t sB;
    cudaStreamCreateWithFlags(&sB, cudaStreamNonBlocking);
    cudaEvent_t evF, evJ;
    cudaEventCreateWithFlags(&evF, cudaEventDisableTiming);
    cudaEventCreateWithFlags(&evJ, cudaEventDisableTiming);

    // ---- prep (conv + transposes + cnt zero + detect) ----
    prep_kernel<<<pblk, 256>>>(x, xb, Wl1, Wr1, w1lt, w1rt, Wl2, Wr2, w2t,
                               cnt, (const int*)ei, n32, n);

    // ---- fork: xpart = x@Wr1 + bl1 on side stream ----
    cudaEventRecord(evF, 0);
    cudaStreamWaitEvent(sB, evF, 0);
    mma_gemm<3><<<mblk, 256, 65536, sB>>>(x, w1rt, bl1, nullptr, xp, nullptr, nullptr, n);
    cudaEventRecord(evJ, sB);

    // ---- main branch: CSR build + gather ----
    hist_kernel<<<eblk, 256>>>(ei, cnt, ne);
    scan_kernel<<<nscan, 512>>>(cnt, rowptr, cur, total, n);
    fill_kernel<<<eblk, 256>>>(ei, cur, eidx, ne);
    gather_mean128_bf16<<<gblk, 256>>>(xb, rowptr, cnt, eidx, mean, n);

    // ---- join, then h = relu(mean@Wl1 + xpart) ----
    cudaStreamWaitEvent(0, evJ, 0);
    mma_gemm<4><<<mblk, 256, 65536>>>(mean, w1lt, nullptr, xp, h, nullptr, nullptr, n);

    // ---- layer 2 ----
    mma_gemm<2><<<mblk, 256, 65536>>>(h, w2t, nullptr, nullptr, nullptr, y2b, y2hi, n);
    gather_final64<<<gblk, 256>>>(y2b, y2hi, bl2, rowptr, cnt, eidx, out, n);

    // Intentionally do not destroy sB/evF/evJ here: kernel_launch may be
    // executing under stream capture, and destroying capture-referenced
    // objects mid-capture is undefined. Few calls per process; trivial leak.
}

// round 8
// speedup vs baseline: 1.0734x; 1.0734x over previous
#include <cuda_runtime.h>
#include <cuda_bf16.h>
#include <cstdint>
#include <math.h>

// ---------------------------------------------------------------------------
// GraphSAGE 2-layer. CSR gather-mean (bf16 payload) + TF32 mma.sync GEMMs.
// Graph: zero+detect -> fork{ prep: bf16(x), W^T } || { hist -> scan -> fill }
//        -> join -> gather -> h=relu([mean|x]@W1t+bl1) -> y2 -> gather_final.
// ---------------------------------------------------------------------------

#define N_MAX 100000
#define E_MAX 1600000

__device__ float    g_mean[(size_t)N_MAX * 128];
__device__ float    g_h   [(size_t)N_MAX * 128];
__device__ float    g_y2hi[(size_t)N_MAX * 64];
__device__ uint16_t g_xb  [(size_t)N_MAX * 128];   // bf16 bits
__device__ uint16_t g_y2b [(size_t)N_MAX * 64];    // bf16 bits
__device__ float    g_w1t[128 * 256];              // [N=128, K=256] K-major, tf32-rounded
__device__ float    g_w2t[128 * 128];              // [N=128, K=128] K-major, tf32-rounded
__device__ int      g_cnt[N_MAX];
__device__ int      g_cur[N_MAX];
__device__ int      g_rowptr[N_MAX];
__device__ int      g_eidx[E_MAX];
__device__ int      g_total;
__device__ int      g_is64;

// ---------------- helpers ----------------
__device__ __forceinline__ uint32_t f2tf32(float x) {
    uint32_t r;
    asm("cvt.rna.tf32.f32 %0, %1;" : "=r"(r) : "f"(x));
    return r;
}
__device__ __forceinline__ void mma_tf32(float (&c)[4], const uint32_t (&a)[4],
                                         const uint32_t (&b)[2]) {
    asm volatile(
        "mma.sync.aligned.m16n8k8.row.col.f32.tf32.tf32.f32 "
        "{%0,%1,%2,%3}, {%4,%5,%6,%7}, {%8,%9}, {%0,%1,%2,%3};"
        : "+f"(c[0]), "+f"(c[1]), "+f"(c[2]), "+f"(c[3])
        : "r"(a[0]), "r"(a[1]), "r"(a[2]), "r"(a[3]), "r"(b[0]), "r"(b[1]));
}
__device__ __forceinline__ float2 bf2_to_f2(uint32_t v) {
    __nv_bfloat162 b = *reinterpret_cast<__nv_bfloat162*>(&v);
    return __bfloat1622float2(b);
}
__device__ __forceinline__ uint32_t f2_to_bf2(float lo, float hi) {
    __nv_bfloat162 b = __floats2bfloat162_rn(lo, hi);
    return *reinterpret_cast<uint32_t*>(&b);
}
__device__ __forceinline__ uint32_t smem_u32(const void* p) {
    uint32_t a;
    asm("{ .reg .u64 t; cvta.to.shared.u64 t, %1; cvt.u32.u64 %0, t; }"
        : "=r"(a) : "l"(p));
    return a;
}
__device__ __forceinline__ void cp_async16(uint32_t smem, const void* g, int src_bytes) {
    asm volatile("cp.async.ca.shared.global [%0], [%1], 16, %2;"
                 :: "r"(smem), "l"(g), "r"(src_bytes) : "memory");
}
#define CP_COMMIT() asm volatile("cp.async.commit_group;" ::: "memory")
#define CP_WAIT0()  asm volatile("cp.async.wait_group 0;" ::: "memory")
#define CP_WAIT1()  asm volatile("cp.async.wait_group 1;" ::: "memory")

__device__ __forceinline__ int swz(int r, int k) {
    return (r << 5) + ((k & ~3) ^ ((r & 7) << 2)) + (k & 3);
}

// ---------------- CSR build ----------------
__device__ __forceinline__ int edge_at(const void* ei, long long idx, int is64) {
    if (is64) return (int)((const long long*)ei)[idx];
    return ((const int*)ei)[idx];
}
__global__ void zero_detect_kernel(int* __restrict__ cnt, const int* __restrict__ ei, int n) {
    int i = blockIdx.x * blockDim.x + threadIdx.x;
    if (i < n) cnt[i] = 0;
    if (i == 0) {
        int nz = 0;
        for (int q = 1; q < 256; q += 2) nz += (ei[q] != 0);
        g_is64 = (nz == 0) ? 1 : 0;
        g_total = 0;
    }
}
__global__ void hist_kernel(const void* __restrict__ ei, int* __restrict__ cnt, int ne) {
    int i = blockIdx.x * blockDim.x + threadIdx.x;
    int is64 = g_is64;
    if (i < ne) atomicAdd(&cnt[edge_at(ei, (long long)ne + i, is64)], 1);
}
// order-free scan: per-block Hillis + atomic ticket for block base.
__global__ void scan_kernel(const int* __restrict__ cnt, int* __restrict__ rowptr,
                            int* __restrict__ cur, int* __restrict__ total, int n) {
    __shared__ int sh[512];
    __shared__ int base_s;
    int tid = threadIdx.x;
    int i = blockIdx.x * 512 + tid;
    int v = (i < n) ? cnt[i] : 0;
    sh[tid] = v;
    __syncthreads();
    for (int off = 1; off < 512; off <<= 1) {
        int t = (tid >= off) ? sh[tid - off] : 0;
        __syncthreads();
        sh[tid] += t;
        __syncthreads();
    }
    if (tid == 511) base_s = atomicAdd(total, sh[511]);
    __syncthreads();
    int excl = sh[tid] - v + base_s;
    if (i < n) { rowptr[i] = excl; cur[i] = excl; }
}
__global__ void fill_kernel(const void* __restrict__ ei, int* __restrict__ cur,
                            int* __restrict__ eidx, int ne) {
    int i = blockIdx.x * blockDim.x + threadIdx.x;
    int is64 = g_is64;
    if (i < ne) {
        int s = edge_at(ei, i, is64);
        int d = edge_at(ei, (long long)ne + i, is64);
        eidx[atomicAdd(&cur[d], 1)] = s;
    }
}

// ---------------- prep: x->bf16, W transposes (tf32-rounded) ----------------
__global__ void prep_kernel(const float* __restrict__ x, uint16_t* __restrict__ xb,
                            const float* __restrict__ Wl1, const float* __restrict__ Wr1,
                            float* __restrict__ W1t,
                            const float* __restrict__ Wl2, const float* __restrict__ Wr2,
                            float* __restrict__ W2t, int n32) {
    int i = blockIdx.x * blockDim.x + threadIdx.x;
    if (i < n32) {
        float4 v = __ldg((const float4*)x + i);
        uint2 o;
        o.x = f2_to_bf2(v.x, v.y);
        o.y = f2_to_bf2(v.z, v.w);
        *((uint2*)xb + i) = o;
        return;
    }
    int j = i - n32;
    if (j < 128 * 256) {
        int nn = j >> 8, k = j & 255;
        float v = (k < 128) ? Wl1[k * 128 + nn] : Wr1[(k - 128) * 128 + nn];
        W1t[j] = __uint_as_float(f2tf32(v));
    } else if (j < 128 * 256 + 128 * 128) {
        int jj = j - 128 * 256;
        int nn = jj >> 7, k = jj & 127;
        float v = (nn < 64) ? Wl2[k * 64 + nn] : Wr2[k * 64 + (nn - 64)];
        W2t[jj] = __uint_as_float(f2tf32(v));
    }
}

// ---------------- gathers (unroll-8; end = beg + cnt) ----------------
__global__ void gather_mean128_bf16(const uint16_t* __restrict__ featb,
                                    const int* __restrict__ rowptr,
                                    const int* __restrict__ cnt,
                                    const int* __restrict__ eidx,
                                    float* __restrict__ mean, int n) {
    int node = (blockIdx.x * blockDim.x + threadIdx.x) >> 5;
    if (node >= n) return;
    int lane = threadIdx.x & 31;
    int beg = __ldg(&rowptr[node]);
    int deg = __ldg(&cnt[node]);
    int end = beg + deg;
    float4 acc = make_float4(0.f, 0.f, 0.f, 0.f);
    const uint2* fb = (const uint2*)featb;
    int j = beg;
    for (; j + 7 < end; j += 8) {
        int s[8];
#pragma unroll
        for (int q = 0; q < 8; q++) s[q] = __ldg(&eidx[j + q]);
        uint2 v[8];
#pragma unroll
        for (int q = 0; q < 8; q++) v[q] = __ldg(&fb[(size_t)s[q] * 32 + lane]);
#pragma unroll
        for (int q = 0; q < 8; q++) {
            float2 a0 = bf2_to_f2(v[q].x), a1 = bf2_to_f2(v[q].y);
            acc.x += a0.x; acc.y += a0.y; acc.z += a1.x; acc.w += a1.y;
        }
    }
    for (; j + 1 < end; j += 2) {
        int s0 = __ldg(&eidx[j]), s1 = __ldg(&eidx[j + 1]);
        uint2 v0 = __ldg(&fb[(size_t)s0 * 32 + lane]);
        uint2 v1 = __ldg(&fb[(size_t)s1 * 32 + lane]);
        float2 a0 = bf2_to_f2(v0.x), a1 = bf2_to_f2(v0.y);
        float2 b0 = bf2_to_f2(v1.x), b1 = bf2_to_f2(v1.y);
        acc.x += a0.x + b0.x; acc.y += a0.y + b0.y;
        acc.z += a1.x + b1.x; acc.w += a1.y + b1.y;
    }
    if (j < end) {
        int s0 = __ldg(&eidx[j]);
        uint2 v0 = __ldg(&fb[(size_t)s0 * 32 + lane]);
        float2 a0 = bf2_to_f2(v0.x), a1 = bf2_to_f2(v0.y);
        acc.x += a0.x; acc.y += a0.y; acc.z += a1.x; acc.w += a1.y;
    }
    float inv = 1.0f / fmaxf((float)deg, 1.0f);
    acc.x *= inv; acc.y *= inv; acc.z *= inv; acc.w *= inv;
    ((float4*)mean)[(size_t)node * 32 + lane] = acc;
}

__global__ void gather_final64(const uint16_t* __restrict__ y2b,
                               const float* __restrict__ y2hi,
                               const float* __restrict__ bl2,
                               const int* __restrict__ rowptr,
                               const int* __restrict__ cnt,
                               const int* __restrict__ eidx,
                               float* __restrict__ out, int n) {
    int node = (blockIdx.x * blockDim.x + threadIdx.x) >> 5;
    if (node >= n) return;
    int lane = threadIdx.x & 31;
    int beg = __ldg(&rowptr[node]);
    int deg = __ldg(&cnt[node]);
    int end = beg + deg;
    float2 acc = make_float2(0.f, 0.f);
    const uint32_t* fb = (const uint32_t*)y2b;
    int j = beg;
    for (; j + 7 < end; j += 8) {
        int s[8];
#pragma unroll
        for (int q = 0; q < 8; q++) s[q] = __ldg(&eidx[j + q]);
        uint32_t v[8];
#pragma unroll
        for (int q = 0; q < 8; q++) v[q] = __ldg(&fb[(size_t)s[q] * 32 + lane]);
#pragma unroll
        for (int q = 0; q < 8; q++) {
            float2 f = bf2_to_f2(v[q]);
            acc.x += f.x; acc.y += f.y;
        }
    }
    for (; j < end; ++j) {
        int s0 = __ldg(&eidx[j]);
        float2 v0 = bf2_to_f2(__ldg(&fb[(size_t)s0 * 32 + lane]));
        acc.x += v0.x; acc.y += v0.y;
    }
    float inv = 1.0f / fmaxf((float)deg, 1.0f);
    float2 yh = *(const float2*)(y2hi + (size_t)node * 64 + lane * 2);
    float2 bb = *(const float2*)(bl2 + lane * 2);
    float2 o;
    o.x = 1.0f / (1.0f + __expf(-(acc.x * inv + yh.x + bb.x)));
    o.y = 1.0f / (1.0f + __expf(-(acc.y * inv + yh.y + bb.y)));
    *(float2*)(out + (size_t)node * 64 + lane * 2) = o;
}

// ---------------------------------------------------------------------------
// TF32 mma.sync GEMM, cp.async double-buffered, XOR-swizzled SMEM.
// C[128-tile,128] = A[*,KTOT] @ Wt^T (Wt: [128,KTOT] K-major, tf32-rounded).
// EPI 1: relu(c+bias) -> f32 out[n,128]
// EPI 2: cols<64 -> bf16 outb[n,64]; cols>=64 -> f32 outhi[n,64]
// ---------------------------------------------------------------------------
template<int KTOT, int HAS_A1, int EPI>
__global__ void __launch_bounds__(256, 2)
mma_gemm(const float* __restrict__ A0, const float* __restrict__ A1,
         const float* __restrict__ Wt, const float* __restrict__ bias,
         float* __restrict__ out, uint16_t* __restrict__ outb,
         float* __restrict__ outhi, int n)
{
    constexpr int NCHUNK = KTOT / 32;
    extern __shared__ float smem[];
    const uint32_t* As = (const uint32_t*)smem;           // [2][4096]
    const uint32_t* Ws = (const uint32_t*)(smem + 8192);  // [2][4096]

    const int tid  = threadIdx.x;
    const int wid  = tid >> 5;
    const int lane = tid & 31;
    const int wm   = wid & 1;
    const int wn   = wid >> 1;
    const int g    = lane >> 2;
    const int tg   = lane & 3;
    const int row0 = blockIdx.x * 128;

    const uint32_t as_b = smem_u32(smem);
    const uint32_t ws_b = as_b + 8192 * 4;

    float c[4][4][4];
#pragma unroll
    for (int mi = 0; mi < 4; mi++)
#pragma unroll
        for (int ni = 0; ni < 4; ni++)
#pragma unroll
            for (int j = 0; j < 4; j++) c[mi][ni][j] = 0.f;

    auto prefetch = [&](int ch, int stage) {
        const int kcol = ch * 32;
        const float* Asrc = A0;
        int kk = kcol;
        if (HAS_A1 && kcol >= 128) { Asrc = A1; kk = kcol - 128; }
        const uint32_t sofs = (uint32_t)stage << 14;
#pragma unroll
        for (int i = tid; i < 1024; i += 256) {
            int r = i >> 3, k4 = i & 7;
            uint32_t widx = (uint32_t)((r << 5) + ((k4 << 2) ^ ((r & 7) << 2)));
            int node = row0 + r;
            int ok = (node < n);
            const float* gA = Asrc + (size_t)(ok ? node : 0) * 128 + kk + (k4 << 2);
            cp_async16(as_b + sofs + widx * 4, gA, ok ? 16 : 0);
            const float* gW = Wt + (size_t)r * KTOT + kcol + (k4 << 2);
            cp_async16(ws_b + sofs + widx * 4, gW, 16);
        }
        CP_COMMIT();
    };

    prefetch(0, 0);

#pragma unroll 1
    for (int ch = 0; ch < NCHUNK; ++ch) {
        const int stage = ch & 1;
        if (ch + 1 < NCHUNK) {
            prefetch(ch + 1, stage ^ 1);
            CP_WAIT1();
        } else {
            CP_WAIT0();
        }
        __syncthreads();

        const uint32_t* Ab = As + (stage << 12);
        const uint32_t* Wb = Ws + (stage << 12);

#pragma unroll
        for (int ks = 0; ks < 4; ++ks) {
            const int k0 = ks * 8;
            uint32_t a[4][4];
#pragma unroll
            for (int mi = 0; mi < 4; mi++) {
                int r0 = wm * 64 + mi * 16 + g;
                a[mi][0] = Ab[swz(r0,     k0 + tg)];
                a[mi][1] = Ab[swz(r0 + 8, k0 + tg)];
                a[mi][2] = Ab[swz(r0,     k0 + tg + 4)];
                a[mi][3] = Ab[swz(r0 + 8, k0 + tg + 4)];
            }
#pragma unroll
            for (int ni = 0; ni < 4; ni++) {
                int nb = wn * 32 + ni * 8 + g;
                uint32_t b[2];
                b[0] = Wb[swz(nb, k0 + tg)];
                b[1] = Wb[swz(nb, k0 + tg + 4)];
#pragma unroll
                for (int mi = 0; mi < 4; mi++)
                    mma_tf32(c[mi][ni], a[mi], b);
            }
        }
        __syncthreads();
    }

#pragma unroll
    for (int mi = 0; mi < 4; mi++) {
#pragma unroll
        for (int half = 0; half < 2; half++) {
            int row = row0 + wm * 64 + mi * 16 + g + half * 8;
            if (row < n) {
#pragma unroll
                for (int ni = 0; ni < 4; ni++) {
                    int col = wn * 32 + ni * 8 + tg * 2;
                    float v0 = c[mi][ni][half * 2 + 0];
                    float v1 = c[mi][ni][half * 2 + 1];
                    if (EPI == 1) {
                        v0 = fmaxf(v0 + __ldg(&bias[col]), 0.f);
                        v1 = fmaxf(v1 + __ldg(&bias[col + 1]), 0.f);
                        *(float2*)(out + (size_t)row * 128 + col) = make_float2(v0, v1);
                    } else {
                        if (col < 64) {
                            *(uint32_t*)(outb + (size_t)row * 64 + col) = f2_to_bf2(v0, v1);
                        } else {
                            *(float2*)(outhi + (size_t)row * 64 + (col - 64)) =
                                make_float2(v0, v1);
                        }
                    }
                }
            }
        }
    }
}

// ---------------------------------------------------------------------------
extern "C" void kernel_launch(void* const* d_in, const int* in_sizes, int n_in,
                              void* d_out, int out_size) {
    const float* x   = (const float*)d_in[0];
    const void*  ei  = d_in[1];
    const float* Wl1 = (const float*)d_in[2];
    const float* bl1 = (const float*)d_in[3];
    const float* Wr1 = (const float*)d_in[4];
    const float* Wl2 = (const float*)d_in[5];
    const float* bl2 = (const float*)d_in[6];
    const float* Wr2 = (const float*)d_in[7];
    float* out = (float*)d_out;

    const int n  = in_sizes[0] / 128;   // 100000
    const int ne = in_sizes[1] / 2;     // 1600000

    float *mean, *h, *y2hi, *w1t, *w2t;
    uint16_t *xb, *y2b;
    int *cnt, *cur, *rowptr, *eidx, *total;
    cudaGetSymbolAddress((void**)&mean,   g_mean);
    cudaGetSymbolAddress((void**)&h,      g_h);
    cudaGetSymbolAddress((void**)&y2hi,   g_y2hi);
    cudaGetSymbolAddress((void**)&xb,     g_xb);
    cudaGetSymbolAddress((void**)&y2b,    g_y2b);
    cudaGetSymbolAddress((void**)&w1t,    g_w1t);
    cudaGetSymbolAddress((void**)&w2t,    g_w2t);
    cudaGetSymbolAddress((void**)&cnt,    g_cnt);
    cudaGetSymbolAddress((void**)&cur,    g_cur);
    cudaGetSymbolAddress((void**)&rowptr, g_rowptr);
    cudaGetSymbolAddress((void**)&eidx,   g_eidx);
    cudaGetSymbolAddress((void**)&total,  g_total);

    cudaFuncSetAttribute(mma_gemm<256, 1, 1>,
                         cudaFuncAttributeMaxDynamicSharedMemorySize, 65536);
    cudaFuncSetAttribute(mma_gemm<128, 0, 2>,
                         cudaFuncAttributeMaxDynamicSharedMemorySize, 65536);

    const int nscan = (n + 511) / 512;
    const int eblk  = (ne + 255) / 256;
    const int gblk  = (n + 7) / 8;
    const int mblk  = (n + 127) / 128;
    const int n32   = n * 32;
    const int pitems = n32 + 128 * 256 + 128 * 128;
    const int pblk  = (pitems + 255) / 256;

    // Fork resources (host-side only; intentionally not destroyed — see R6/R7
    // note about capture-referenced objects).
    cudaStream_t sB;
    cudaStreamCreateWithFlags(&sB, cudaStreamNonBlocking);
    cudaEvent_t evF, evJ;
    cudaEventCreateWithFlags(&evF, cudaEventDisableTiming);
    cudaEventCreateWithFlags(&evJ, cudaEventDisableTiming);

    // ---- root: zero cnt + detect ----
    zero_detect_kernel<<<(n + 255) / 256, 256>>>(cnt, (const int*)ei, n);

    // ---- fork: prep on side stream (bf16 conv + W transposes) ----
    cudaEventRecord(evF, 0);
    cudaStreamWaitEvent(sB, evF, 0);
    prep_kernel<<<pblk, 256, 0, sB>>>(x, xb, Wl1, Wr1, w1t, Wl2, Wr2, w2t, n32);
    cudaEventRecord(evJ, sB);

    // ---- main: CSR build ----
    hist_kernel<<<eblk, 256>>>(ei, cnt, ne);
    scan_kernel<<<nscan, 512>>>(cnt, rowptr, cur, total, n);
    fill_kernel<<<eblk, 256>>>(ei, cur, eidx, ne);

    // ---- join, then layer 1 ----
    cudaStreamWaitEvent(0, evJ, 0);
    gather_mean128_bf16<<<gblk, 256>>>(xb, rowptr, cnt, eidx, mean, n);
    mma_gemm<256, 1, 1><<<mblk, 256, 65536>>>(mean, x, w1t, bl1, h, nullptr, nullptr, n);

    // ---- layer 2 ----
    mma_gemm<128, 0, 2><<<mblk, 256, 65536>>>(h, nullptr, w2t, nullptr, nullptr, y2b, y2hi, n);
    gather_final64<<<gblk, 256>>>(y2b, y2hi, bl2, rowptr, cnt, eidx, out, n);
}

// round 9
// speedup vs baseline: 1.1390x; 1.0612x over previous
#include <cuda_runtime.h>
#include <cuda_bf16.h>
#include <cstdint>
#include <math.h>

// ---------------------------------------------------------------------------
// GraphSAGE 2-layer. CSR gather-mean (bf16 payload, wide 16B-lane loads) +
// TF32 mma.sync GEMMs (cp.async double-buffered, XOR-swizzled SMEM).
// Graph: zero+detect -> fork{ prep } || { hist -> scan -> fill }
//        -> join -> gather -> h=relu([mean|x]@W1t+bl1) -> y2 -> gather_final.
// ---------------------------------------------------------------------------

#define N_MAX 100000
#define E_MAX 1600000

__device__ float    g_mean[(size_t)N_MAX * 128];
__device__ float    g_h   [(size_t)N_MAX * 128];
__device__ float    g_y2hi[(size_t)N_MAX * 64];
__device__ uint16_t g_xb  [(size_t)N_MAX * 128];   // bf16 bits
__device__ uint16_t g_y2b [(size_t)N_MAX * 64];    // bf16 bits
__device__ float    g_w1t[128 * 256];              // [N=128, K=256] K-major, tf32-rounded
__device__ float    g_w2t[128 * 128];              // [N=128, K=128] K-major, tf32-rounded
__device__ int      g_cnt[N_MAX];
__device__ int      g_cur[N_MAX];
__device__ int      g_rowptr[N_MAX];
__device__ int      g_eidx[E_MAX];
__device__ int      g_total;
__device__ int      g_is64;

// ---------------- helpers ----------------
__device__ __forceinline__ uint32_t f2tf32(float x) {
    uint32_t r;
    asm("cvt.rna.tf32.f32 %0, %1;" : "=r"(r) : "f"(x));
    return r;
}
__device__ __forceinline__ void mma_tf32(float (&c)[4], const uint32_t (&a)[4],
                                         const uint32_t (&b)[2]) {
    asm volatile(
        "mma.sync.aligned.m16n8k8.row.col.f32.tf32.tf32.f32 "
        "{%0,%1,%2,%3}, {%4,%5,%6,%7}, {%8,%9}, {%0,%1,%2,%3};"
        : "+f"(c[0]), "+f"(c[1]), "+f"(c[2]), "+f"(c[3])
        : "r"(a[0]), "r"(a[1]), "r"(a[2]), "r"(a[3]), "r"(b[0]), "r"(b[1]));
}
__device__ __forceinline__ float2 bf2_to_f2(uint32_t v) {
    __nv_bfloat162 b = *reinterpret_cast<__nv_bfloat162*>(&v);
    return __bfloat1622float2(b);
}
__device__ __forceinline__ uint32_t f2_to_bf2(float lo, float hi) {
    __nv_bfloat162 b = __floats2bfloat162_rn(lo, hi);
    return *reinterpret_cast<uint32_t*>(&b);
}
__device__ __forceinline__ void acc_bf8(float (&acc)[8], uint4 v) {
    float2 f0 = bf2_to_f2(v.x), f1 = bf2_to_f2(v.y);
    float2 f2 = bf2_to_f2(v.z), f3 = bf2_to_f2(v.w);
    acc[0] += f0.x; acc[1] += f0.y; acc[2] += f1.x; acc[3] += f1.y;
    acc[4] += f2.x; acc[5] += f2.y; acc[6] += f3.x; acc[7] += f3.y;
}
__device__ __forceinline__ uint32_t smem_u32(const void* p) {
    uint32_t a;
    asm("{ .reg .u64 t; cvta.to.shared.u64 t, %1; cvt.u32.u64 %0, t; }"
        : "=r"(a) : "l"(p));
    return a;
}
__device__ __forceinline__ void cp_async16(uint32_t smem, const void* g, int src_bytes) {
    asm volatile("cp.async.ca.shared.global [%0], [%1], 16, %2;"
                 :: "r"(smem), "l"(g), "r"(src_bytes) : "memory");
}
#define CP_COMMIT() asm volatile("cp.async.commit_group;" ::: "memory")
#define CP_WAIT0()  asm volatile("cp.async.wait_group 0;" ::: "memory")
#define CP_WAIT1()  asm volatile("cp.async.wait_group 1;" ::: "memory")

__device__ __forceinline__ int swz(int r, int k) {
    return (r << 5) + ((k & ~3) ^ ((r & 7) << 2)) + (k & 3);
}

// ---------------- CSR build ----------------
__device__ __forceinline__ int edge_at(const void* ei, long long idx, int is64) {
    if (is64) return (int)((const long long*)ei)[idx];
    return ((const int*)ei)[idx];
}
__global__ void zero_detect_kernel(int* __restrict__ cnt, const int* __restrict__ ei, int n) {
    int i = blockIdx.x * blockDim.x + threadIdx.x;
    if (i < n) cnt[i] = 0;
    if (i == 0) {
        int nz = 0;
        for (int q = 1; q < 256; q += 2) nz += (ei[q] != 0);
        g_is64 = (nz == 0) ? 1 : 0;
        g_total = 0;
    }
}
// 2 edges per thread, vectorized dst reads (requires ne even for vector path).
__global__ void hist_kernel(const void* __restrict__ ei, int* __restrict__ cnt, int ne) {
    int i = blockIdx.x * blockDim.x + threadIdx.x;
    int is64 = g_is64;
    int i2 = i * 2;
    if (((ne & 1) == 0) && i2 + 1 < ne) {
        int d0, d1;
        if (is64) {
            longlong2 v = __ldg((const longlong2*)ei + (ne + i2) / 2);
            d0 = (int)v.x; d1 = (int)v.y;
        } else {
            int2 v = __ldg((const int2*)ei + (ne + i2) / 2);
            d0 = v.x; d1 = v.y;
        }
        atomicAdd(&cnt[d0], 1);
        atomicAdd(&cnt[d1], 1);
    } else {
        for (int q = 0; q < 2; q++)
            if (i2 + q < ne)
                atomicAdd(&cnt[edge_at(ei, (long long)ne + i2 + q, is64)], 1);
    }
}
// order-free scan: per-block Hillis + atomic ticket for block base.
__global__ void scan_kernel(const int* __restrict__ cnt, int* __restrict__ rowptr,
                            int* __restrict__ cur, int* __restrict__ total, int n) {
    __shared__ int sh[512];
    __shared__ int base_s;
    int tid = threadIdx.x;
    int i = blockIdx.x * 512 + tid;
    int v = (i < n) ? cnt[i] : 0;
    sh[tid] = v;
    __syncthreads();
    for (int off = 1; off < 512; off <<= 1) {
        int t = (tid >= off) ? sh[tid - off] : 0;
        __syncthreads();
        sh[tid] += t;
        __syncthreads();
    }
    if (tid == 511) base_s = atomicAdd(total, sh[511]);
    __syncthreads();
    int excl = sh[tid] - v + base_s;
    if (i < n) { rowptr[i] = excl; cur[i] = excl; }
}
// 2 edges per thread, vectorized src+dst reads.
__global__ void fill_kernel(const void* __restrict__ ei, int* __restrict__ cur,
                            int* __restrict__ eidx, int ne) {
    int i = blockIdx.x * blockDim.x + threadIdx.x;
    int is64 = g_is64;
    int i2 = i * 2;
    if (((ne & 1) == 0) && i2 + 1 < ne) {
        int s0, s1, d0, d1;
        if (is64) {
            longlong2 sv = __ldg((const longlong2*)ei + i2 / 2);
            longlong2 dv = __ldg((const longlong2*)ei + (ne + i2) / 2);
            s0 = (int)sv.x; s1 = (int)sv.y;
            d0 = (int)dv.x; d1 = (int)dv.y;
        } else {
            int2 sv = __ldg((const int2*)ei + i2 / 2);
            int2 dv = __ldg((const int2*)ei + (ne + i2) / 2);
            s0 = sv.x; s1 = sv.y;
            d0 = dv.x; d1 = dv.y;
        }
        eidx[atomicAdd(&cur[d0], 1)] = s0;
        eidx[atomicAdd(&cur[d1], 1)] = s1;
    } else {
        for (int q = 0; q < 2; q++)
            if (i2 + q < ne) {
                int s = edge_at(ei, i2 + q, is64);
                int d = edge_at(ei, (long long)ne + i2 + q, is64);
                eidx[atomicAdd(&cur[d], 1)] = s;
            }
    }
}

// ---------------- prep: x->bf16, W transposes (tf32-rounded) ----------------
__global__ void prep_kernel(const float* __restrict__ x, uint16_t* __restrict__ xb,
                            const float* __restrict__ Wl1, const float* __restrict__ Wr1,
                            float* __restrict__ W1t,
                            const float* __restrict__ Wl2, const float* __restrict__ Wr2,
                            float* __restrict__ W2t, int n32) {
    int i = blockIdx.x * blockDim.x + threadIdx.x;
    if (i < n32) {
        float4 v = __ldg((const float4*)x + i);
        uint2 o;
        o.x = f2_to_bf2(v.x, v.y);
        o.y = f2_to_bf2(v.z, v.w);
        *((uint2*)xb + i) = o;
        return;
    }
    int j = i - n32;
    if (j < 128 * 256) {
        int nn = j >> 8, k = j & 255;
        float v = (k < 128) ? Wl1[k * 128 + nn] : Wr1[(k - 128) * 128 + nn];
        W1t[j] = __uint_as_float(f2tf32(v));
    } else if (j < 128 * 256 + 128 * 128) {
        int jj = j - 128 * 256;
        int nn = jj >> 7, k = jj & 127;
        float v = (nn < 64) ? Wl2[k * 64 + nn] : Wr2[k * 64 + (nn - 64)];
        W2t[jj] = __uint_as_float(f2tf32(v));
    }
}

// ---------------- wide gathers ----------------
// gather128: half-warp per node. Row = 128 bf16 = 256B = 16 lanes x uint4.
__global__ void gather_mean128_w(const uint16_t* __restrict__ featb,
                                 const int* __restrict__ rowptr,
                                 const int* __restrict__ cnt,
                                 const int* __restrict__ eidx,
                                 float* __restrict__ mean, int n) {
    int gw   = (blockIdx.x * blockDim.x + threadIdx.x) >> 5;
    int lane = threadIdx.x & 31;
    int node = gw * 2 + (lane >> 4);
    int sl   = lane & 15;
    if (node >= n) return;
    int beg = __ldg(&rowptr[node]);
    int deg = __ldg(&cnt[node]);
    int end = beg + deg;
    const uint4* fb = (const uint4*)featb;   // 16 uint4 per row
    float acc[8] = {0.f, 0.f, 0.f, 0.f, 0.f, 0.f, 0.f, 0.f};
    int j = beg;
    for (; j + 3 < end; j += 4) {
        int s0 = __ldg(&eidx[j]),     s1 = __ldg(&eidx[j + 1]);
        int s2 = __ldg(&eidx[j + 2]), s3 = __ldg(&eidx[j + 3]);
        uint4 v0 = __ldg(&fb[(size_t)s0 * 16 + sl]);
        uint4 v1 = __ldg(&fb[(size_t)s1 * 16 + sl]);
        uint4 v2 = __ldg(&fb[(size_t)s2 * 16 + sl]);
        uint4 v3 = __ldg(&fb[(size_t)s3 * 16 + sl]);
        acc_bf8(acc, v0); acc_bf8(acc, v1); acc_bf8(acc, v2); acc_bf8(acc, v3);
    }
    for (; j < end; ++j) {
        int s0 = __ldg(&eidx[j]);
        uint4 v0 = __ldg(&fb[(size_t)s0 * 16 + sl]);
        acc_bf8(acc, v0);
    }
    float inv = 1.0f / fmaxf((float)deg, 1.0f);
    float* mp = mean + (size_t)node * 128 + sl * 8;
    *(float4*)mp       = make_float4(acc[0] * inv, acc[1] * inv, acc[2] * inv, acc[3] * inv);
    *(float4*)(mp + 4) = make_float4(acc[4] * inv, acc[5] * inv, acc[6] * inv, acc[7] * inv);
}

// gather_final64: quarter-warp per node. Row = 64 bf16 = 128B = 8 lanes x uint4.
__global__ void gather_final64_w(const uint16_t* __restrict__ y2b,
                                 const float* __restrict__ y2hi,
                                 const float* __restrict__ bl2,
                                 const int* __restrict__ rowptr,
                                 const int* __restrict__ cnt,
                                 const int* __restrict__ eidx,
                                 float* __restrict__ out, int n) {
    int gw   = (blockIdx.x * blockDim.x + threadIdx.x) >> 5;
    int lane = threadIdx.x & 31;
    int node = gw * 4 + (lane >> 3);
    int sl   = lane & 7;
    if (node >= n) return;
    int beg = __ldg(&rowptr[node]);
    int deg = __ldg(&cnt[node]);
    int end = beg + deg;
    const uint4* fb = (const uint4*)y2b;     // 8 uint4 per row
    float acc[8] = {0.f, 0.f, 0.f, 0.f, 0.f, 0.f, 0.f, 0.f};
    int j = beg;
    for (; j + 3 < end; j += 4) {
        int s0 = __ldg(&eidx[j]),     s1 = __ldg(&eidx[j + 1]);
        int s2 = __ldg(&eidx[j + 2]), s3 = __ldg(&eidx[j + 3]);
        uint4 v0 = __ldg(&fb[(size_t)s0 * 8 + sl]);
        uint4 v1 = __ldg(&fb[(size_t)s1 * 8 + sl]);
        uint4 v2 = __ldg(&fb[(size_t)s2 * 8 + sl]);
        uint4 v3 = __ldg(&fb[(size_t)s3 * 8 + sl]);
        acc_bf8(acc, v0); acc_bf8(acc, v1); acc_bf8(acc, v2); acc_bf8(acc, v3);
    }
    for (; j < end; ++j) {
        int s0 = __ldg(&eidx[j]);
        uint4 v0 = __ldg(&fb[(size_t)s0 * 8 + sl]);
        acc_bf8(acc, v0);
    }
    float inv = 1.0f / fmaxf((float)deg, 1.0f);
    const float* yp = y2hi + (size_t)node * 64 + sl * 8;
    const float* bp = bl2 + sl * 8;
    float4 y0 = *(const float4*)yp, y1 = *(const float4*)(yp + 4);
    float4 b0 = *(const float4*)bp, b1 = *(const float4*)(bp + 4);
    float4 o0, o1;
    o0.x = 1.0f / (1.0f + __expf(-(acc[0] * inv + y0.x + b0.x)));
    o0.y = 1.0f / (1.0f + __expf(-(acc[1] * inv + y0.y + b0.y)));
    o0.z = 1.0f / (1.0f + __expf(-(acc[2] * inv + y0.z + b0.z)));
    o0.w = 1.0f / (1.0f + __expf(-(acc[3] * inv + y0.w + b0.w)));
    o1.x = 1.0f / (1.0f + __expf(-(acc[4] * inv + y1.x + b1.x)));
    o1.y = 1.0f / (1.0f + __expf(-(acc[5] * inv + y1.y + b1.y)));
    o1.z = 1.0f / (1.0f + __expf(-(acc[6] * inv + y1.z + b1.z)));
    o1.w = 1.0f / (1.0f + __expf(-(acc[7] * inv + y1.w + b1.w)));
    float* op = out + (size_t)node * 64 + sl * 8;
    *(float4*)op       = o0;
    *(float4*)(op + 4) = o1;
}

// ---------------------------------------------------------------------------
// TF32 mma.sync GEMM, cp.async double-buffered, XOR-swizzled SMEM.
// C[128-tile,128] = A[*,KTOT] @ Wt^T (Wt: [128,KTOT] K-major, tf32-rounded).
// EPI 1: relu(c+bias) -> f32 out[n,128]
// EPI 2: cols<64 -> bf16 outb[n,64]; cols>=64 -> f32 outhi[n,64]
// ---------------------------------------------------------------------------
template<int KTOT, int HAS_A1, int EPI>
__global__ void __launch_bounds__(256, 2)
mma_gemm(const float* __restrict__ A0, const float* __restrict__ A1,
         const float* __restrict__ Wt, const float* __restrict__ bias,
         float* __restrict__ out, uint16_t* __restrict__ outb,
         float* __restrict__ outhi, int n)
{
    constexpr int NCHUNK = KTOT / 32;
    extern __shared__ float smem[];
    const uint32_t* As = (const uint32_t*)smem;           // [2][4096]
    const uint32_t* Ws = (const uint32_t*)(smem + 8192);  // [2][4096]

    const int tid  = threadIdx.x;
    const int wid  = tid >> 5;
    const int lane = tid & 31;
    const int wm   = wid & 1;
    const int wn   = wid >> 1;
    const int g    = lane >> 2;
    const int tg   = lane & 3;
    const int row0 = blockIdx.x * 128;

    const uint32_t as_b = smem_u32(smem);
    const uint32_t ws_b = as_b + 8192 * 4;

    float c[4][4][4];
#pragma unroll
    for (int mi = 0; mi < 4; mi++)
#pragma unroll
        for (int ni = 0; ni < 4; ni++)
#pragma unroll
            for (int j = 0; j < 4; j++) c[mi][ni][j] = 0.f;

    auto prefetch = [&](int ch, int stage) {
        const int kcol = ch * 32;
        const float* Asrc = A0;
        int kk = kcol;
        if (HAS_A1 && kcol >= 128) { Asrc = A1; kk = kcol - 128; }
        const uint32_t sofs = (uint32_t)stage << 14;
#pragma unroll
        for (int i = tid; i < 1024; i += 256) {
            int r = i >> 3, k4 = i & 7;
            uint32_t widx = (uint32_t)((r << 5) + ((k4 << 2) ^ ((r & 7) << 2)));
            int node = row0 + r;
            int ok = (node < n);
            const float* gA = Asrc + (size_t)(ok ? node : 0) * 128 + kk + (k4 << 2);
            cp_async16(as_b + sofs + widx * 4, gA, ok ? 16 : 0);
            const float* gW = Wt + (size_t)r * KTOT + kcol + (k4 << 2);
            cp_async16(ws_b + sofs + widx * 4, gW, 16);
        }
        CP_COMMIT();
    };

    prefetch(0, 0);

#pragma unroll 1
    for (int ch = 0; ch < NCHUNK; ++ch) {
        const int stage = ch & 1;
        if (ch + 1 < NCHUNK) {
            prefetch(ch + 1, stage ^ 1);
            CP_WAIT1();
        } else {
            CP_WAIT0();
        }
        __syncthreads();

        const uint32_t* Ab = As + (stage << 12);
        const uint32_t* Wb = Ws + (stage << 12);

#pragma unroll
        for (int ks = 0; ks < 4; ++ks) {
            const int k0 = ks * 8;
            uint32_t a[4][4];
#pragma unroll
            for (int mi = 0; mi < 4; mi++) {
                int r0 = wm * 64 + mi * 16 + g;
                a[mi][0] = Ab[swz(r0,     k0 + tg)];
                a[mi][1] = Ab[swz(r0 + 8, k0 + tg)];
                a[mi][2] = Ab[swz(r0,     k0 + tg + 4)];
                a[mi][3] = Ab[swz(r0 + 8, k0 + tg + 4)];
            }
#pragma unroll
            for (int ni = 0; ni < 4; ni++) {
                int nb = wn * 32 + ni * 8 + g;
                uint32_t b[2];
                b[0] = Wb[swz(nb, k0 + tg)];
                b[1] = Wb[swz(nb, k0 + tg + 4)];
#pragma unroll
                for (int mi = 0; mi < 4; mi++)
                    mma_tf32(c[mi][ni], a[mi], b);
            }
        }
        __syncthreads();
    }

#pragma unroll
    for (int mi = 0; mi < 4; mi++) {
#pragma unroll
        for (int half = 0; half < 2; half++) {
            int row = row0 + wm * 64 + mi * 16 + g + half * 8;
            if (row < n) {
#pragma unroll
                for (int ni = 0; ni < 4; ni++) {
                    int col = wn * 32 + ni * 8 + tg * 2;
                    float v0 = c[mi][ni][half * 2 + 0];
                    float v1 = c[mi][ni][half * 2 + 1];
                    if (EPI == 1) {
                        v0 = fmaxf(v0 + __ldg(&bias[col]), 0.f);
                        v1 = fmaxf(v1 + __ldg(&bias[col + 1]), 0.f);
                        *(float2*)(out + (size_t)row * 128 + col) = make_float2(v0, v1);
                    } else {
                        if (col < 64) {
                            *(uint32_t*)(outb + (size_t)row * 64 + col) = f2_to_bf2(v0, v1);
                        } else {
                            *(float2*)(outhi + (size_t)row * 64 + (col - 64)) =
                                make_float2(v0, v1);
                        }
                    }
                }
            }
        }
    }
}

// ---------------------------------------------------------------------------
extern "C" void kernel_launch(void* const* d_in, const int* in_sizes, int n_in,
                              void* d_out, int out_size) {
    const float* x   = (const float*)d_in[0];
    const void*  ei  = d_in[1];
    const float* Wl1 = (const float*)d_in[2];
    const float* bl1 = (const float*)d_in[3];
    const float* Wr1 = (const float*)d_in[4];
    const float* Wl2 = (const float*)d_in[5];
    const float* bl2 = (const float*)d_in[6];
    const float* Wr2 = (const float*)d_in[7];
    float* out = (float*)d_out;

    const int n  = in_sizes[0] / 128;   // 100000
    const int ne = in_sizes[1] / 2;     // 1600000

    float *mean, *h, *y2hi, *w1t, *w2t;
    uint16_t *xb, *y2b;
    int *cnt, *cur, *rowptr, *eidx, *total;
    cudaGetSymbolAddress((void**)&mean,   g_mean);
    cudaGetSymbolAddress((void**)&h,      g_h);
    cudaGetSymbolAddress((void**)&y2hi,   g_y2hi);
    cudaGetSymbolAddress((void**)&xb,     g_xb);
    cudaGetSymbolAddress((void**)&y2b,    g_y2b);
    cudaGetSymbolAddress((void**)&w1t,    g_w1t);
    cudaGetSymbolAddress((void**)&w2t,    g_w2t);
    cudaGetSymbolAddress((void**)&cnt,    g_cnt);
    cudaGetSymbolAddress((void**)&cur,    g_cur);
    cudaGetSymbolAddress((void**)&rowptr, g_rowptr);
    cudaGetSymbolAddress((void**)&eidx,   g_eidx);
    cudaGetSymbolAddress((void**)&total,  g_total);

    cudaFuncSetAttribute(mma_gemm<256, 1, 1>,
                         cudaFuncAttributeMaxDynamicSharedMemorySize, 65536);
    cudaFuncSetAttribute(mma_gemm<128, 0, 2>,
                         cudaFuncAttributeMaxDynamicSharedMemorySize, 65536);

    const int nscan = (n + 511) / 512;
    const int eblk2 = (ne / 2 + 255) / 256 + 1;
    const int gblk1 = (n + 15) / 16;     // 2 nodes/warp, 8 warps/block
    const int gblk2 = (n + 31) / 32;     // 4 nodes/warp
    const int mblk  = (n + 127) / 128;
    const int n32   = n * 32;
    const int pitems = n32 + 128 * 256 + 128 * 128;
    const int pblk  = (pitems + 255) / 256;

    // Fork resources (host-side only; intentionally not destroyed — capture-
    // referenced objects must outlive the graph).
    cudaStream_t sB;
    cudaStreamCreateWithFlags(&sB, cudaStreamNonBlocking);
    cudaEvent_t evF, evJ;
    cudaEventCreateWithFlags(&evF, cudaEventDisableTiming);
    cudaEventCreateWithFlags(&evJ, cudaEventDisableTiming);

    // ---- root: zero cnt + detect ----
    zero_detect_kernel<<<(n + 255) / 256, 256>>>(cnt, (const int*)ei, n);

    // ---- fork: prep on side stream (bf16 conv + W transposes) ----
    cudaEventRecord(evF, 0);
    cudaStreamWaitEvent(sB, evF, 0);
    prep_kernel<<<pblk, 256, 0, sB>>>(x, xb, Wl1, Wr1, w1t, Wl2, Wr2, w2t, n32);
    cudaEventRecord(evJ, sB);

    // ---- main: CSR build ----
    hist_kernel<<<eblk2, 256>>>(ei, cnt, ne);
    scan_kernel<<<nscan, 512>>>(cnt, rowptr, cur, total, n);
    fill_kernel<<<eblk2, 256>>>(ei, cur, eidx, ne);

    // ---- join, then layer 1 ----
    cudaStreamWaitEvent(0, evJ, 0);
    gather_mean128_w<<<gblk1, 256>>>(xb, rowptr, cnt, eidx, mean, n);
    mma_gemm<256, 1, 1><<<mblk, 256, 65536>>>(mean, x, w1t, bl1, h, nullptr, nullptr, n);

    // ---- layer 2 ----
    mma_gemm<128, 0, 2><<<mblk, 256, 65536>>>(h, nullptr, w2t, nullptr, nullptr, y2b, y2hi, n);
    gather_final64_w<<<gblk2, 256>>>(y2b, y2hi, bl2, rowptr, cnt, eidx, out, n);
}

// round 10
// speedup vs baseline: 1.1945x; 1.0487x over previous
#include <cuda_runtime.h>
#include <cuda_bf16.h>
#include <cstdint>
#include <math.h>

// ---------------------------------------------------------------------------
// GraphSAGE 2-layer. CSR gather-mean (bf16 payload, 16B-lane loads) +
// TF32 mma.sync GEMMs (cp.async double-buffered, XOR-swizzled SMEM).
// Split-half software pipeline: gathers (LTS-bound) overlap GEMMs (tensor).
//   S0: zero+detect, hist, scan, fill, g_A, g_B, m1_B, m2_B, gather_final
//   S1: prep,                    m1_A, m2_A
// ---------------------------------------------------------------------------

#define N_MAX 100000
#define E_MAX 1600000

__device__ float    g_mean[(size_t)N_MAX * 128];
__device__ float    g_h   [(size_t)N_MAX * 128];
__device__ float    g_y2hi[(size_t)N_MAX * 64];
__device__ uint16_t g_xb  [(size_t)N_MAX * 128];   // bf16 bits
__device__ uint16_t g_y2b [(size_t)N_MAX * 64];    // bf16 bits
__device__ float    g_w1t[128 * 256];              // [N=128, K=256] K-major, tf32-rounded
__device__ float    g_w2t[128 * 128];              // [N=128, K=128] K-major, tf32-rounded
__device__ int      g_cnt[N_MAX];
__device__ int      g_cur[N_MAX];
__device__ int      g_rowptr[N_MAX];
__device__ int      g_eidx[E_MAX];
__device__ int      g_total;
__device__ int      g_is64;

// ---------------- helpers ----------------
__device__ __forceinline__ uint32_t f2tf32(float x) {
    uint32_t r;
    asm("cvt.rna.tf32.f32 %0, %1;" : "=r"(r) : "f"(x));
    return r;
}
__device__ __forceinline__ void mma_tf32(float (&c)[4], const uint32_t (&a)[4],
                                         const uint32_t (&b)[2]) {
    asm volatile(
        "mma.sync.aligned.m16n8k8.row.col.f32.tf32.tf32.f32 "
        "{%0,%1,%2,%3}, {%4,%5,%6,%7}, {%8,%9}, {%0,%1,%2,%3};"
        : "+f"(c[0]), "+f"(c[1]), "+f"(c[2]), "+f"(c[3])
        : "r"(a[0]), "r"(a[1]), "r"(a[2]), "r"(a[3]), "r"(b[0]), "r"(b[1]));
}
__device__ __forceinline__ float2 bf2_to_f2(uint32_t v) {
    __nv_bfloat162 b = *reinterpret_cast<__nv_bfloat162*>(&v);
    return __bfloat1622float2(b);
}
__device__ __forceinline__ uint32_t f2_to_bf2(float lo, float hi) {
    __nv_bfloat162 b = __floats2bfloat162_rn(lo, hi);
    return *reinterpret_cast<uint32_t*>(&b);
}
__device__ __forceinline__ void acc_bf8(float (&acc)[8], uint4 v) {
    float2 f0 = bf2_to_f2(v.x), f1 = bf2_to_f2(v.y);
    float2 f2 = bf2_to_f2(v.z), f3 = bf2_to_f2(v.w);
    acc[0] += f0.x; acc[1] += f0.y; acc[2] += f1.x; acc[3] += f1.y;
    acc[4] += f2.x; acc[5] += f2.y; acc[6] += f3.x; acc[7] += f3.y;
}
__device__ __forceinline__ uint32_t smem_u32(const void* p) {
    uint32_t a;
    asm("{ .reg .u64 t; cvta.to.shared.u64 t, %1; cvt.u32.u64 %0, t; }"
        : "=r"(a) : "l"(p));
    return a;
}
__device__ __forceinline__ void cp_async16(uint32_t smem, const void* g, int src_bytes) {
    asm volatile("cp.async.ca.shared.global [%0], [%1], 16, %2;"
                 :: "r"(smem), "l"(g), "r"(src_bytes) : "memory");
}
#define CP_COMMIT() asm volatile("cp.async.commit_group;" ::: "memory")
#define CP_WAIT0()  asm volatile("cp.async.wait_group 0;" ::: "memory")
#define CP_WAIT1()  asm volatile("cp.async.wait_group 1;" ::: "memory")

__device__ __forceinline__ int swz(int r, int k) {
    return (r << 5) + ((k & ~3) ^ ((r & 7) << 2)) + (k & 3);
}

// ---------------- CSR build ----------------
__device__ __forceinline__ int edge_at(const void* ei, long long idx, int is64) {
    if (is64) return (int)((const long long*)ei)[idx];
    return ((const int*)ei)[idx];
}
__global__ void zero_detect_kernel(int* __restrict__ cnt, const int* __restrict__ ei, int n) {
    int i = blockIdx.x * blockDim.x + threadIdx.x;
    if (i < n) cnt[i] = 0;
    if (i == 0) {
        int nz = 0;
        for (int q = 1; q < 256; q += 2) nz += (ei[q] != 0);
        g_is64 = (nz == 0) ? 1 : 0;
        g_total = 0;
    }
}
// 2 edges per thread, vectorized dst reads.
__global__ void hist_kernel(const void* __restrict__ ei, int* __restrict__ cnt, int ne) {
    int i = blockIdx.x * blockDim.x + threadIdx.x;
    int is64 = g_is64;
    int i2 = i * 2;
    if (((ne & 1) == 0) && i2 + 1 < ne) {
        int d0, d1;
        if (is64) {
            longlong2 v = __ldg((const longlong2*)ei + (ne + i2) / 2);
            d0 = (int)v.x; d1 = (int)v.y;
        } else {
            int2 v = __ldg((const int2*)ei + (ne + i2) / 2);
            d0 = v.x; d1 = v.y;
        }
        atomicAdd(&cnt[d0], 1);
        atomicAdd(&cnt[d1], 1);
    } else {
        for (int q = 0; q < 2; q++)
            if (i2 + q < ne)
                atomicAdd(&cnt[edge_at(ei, (long long)ne + i2 + q, is64)], 1);
    }
}
// order-free scan: warp-shuffle scan + atomic ticket for block base.
__global__ void scan_kernel(const int* __restrict__ cnt, int* __restrict__ rowptr,
                            int* __restrict__ cur, int* __restrict__ total, int n) {
    __shared__ int wsum[16];
    __shared__ int base_s;
    int tid = threadIdx.x;                 // 512
    int i = blockIdx.x * 512 + tid;
    int v = (i < n) ? cnt[i] : 0;
    int lane = tid & 31, w = tid >> 5;
    int p = v;
#pragma unroll
    for (int off = 1; off < 32; off <<= 1) {
        int t = __shfl_up_sync(0xFFFFFFFFu, p, off);
        if (lane >= off) p += t;
    }
    if (lane == 31) wsum[w] = p;
    __syncthreads();
    if (w == 0) {
        int s = (lane < 16) ? wsum[lane] : 0;
#pragma unroll
        for (int off = 1; off < 16; off <<= 1) {
            int t = __shfl_up_sync(0xFFFFFFFFu, s, off);
            if (lane >= off) s += t;
        }
        if (lane < 16) wsum[lane] = s;
        if (lane == 15) base_s = atomicAdd(total, s);
    }
    __syncthreads();
    int woff = (w > 0) ? wsum[w - 1] : 0;
    int excl = base_s + woff + p - v;
    if (i < n) { rowptr[i] = excl; cur[i] = excl; }
}
// 2 edges per thread, vectorized src+dst reads.
__global__ void fill_kernel(const void* __restrict__ ei, int* __restrict__ cur,
                            int* __restrict__ eidx, int ne) {
    int i = blockIdx.x * blockDim.x + threadIdx.x;
    int is64 = g_is64;
    int i2 = i * 2;
    if (((ne & 1) == 0) && i2 + 1 < ne) {
        int s0, s1, d0, d1;
        if (is64) {
            longlong2 sv = __ldg((const longlong2*)ei + i2 / 2);
            longlong2 dv = __ldg((const longlong2*)ei + (ne + i2) / 2);
            s0 = (int)sv.x; s1 = (int)sv.y;
            d0 = (int)dv.x; d1 = (int)dv.y;
        } else {
            int2 sv = __ldg((const int2*)ei + i2 / 2);
            int2 dv = __ldg((const int2*)ei + (ne + i2) / 2);
            s0 = sv.x; s1 = sv.y;
            d0 = dv.x; d1 = dv.y;
        }
        eidx[atomicAdd(&cur[d0], 1)] = s0;
        eidx[atomicAdd(&cur[d1], 1)] = s1;
    } else {
        for (int q = 0; q < 2; q++)
            if (i2 + q < ne) {
                int s = edge_at(ei, i2 + q, is64);
                int d = edge_at(ei, (long long)ne + i2 + q, is64);
                eidx[atomicAdd(&cur[d], 1)] = s;
            }
    }
}

// ---------------- prep: x->bf16, W transposes (tf32-rounded) ----------------
__global__ void prep_kernel(const float* __restrict__ x, uint16_t* __restrict__ xb,
                            const float* __restrict__ Wl1, const float* __restrict__ Wr1,
                            float* __restrict__ W1t,
                            const float* __restrict__ Wl2, const float* __restrict__ Wr2,
                            float* __restrict__ W2t, int n32) {
    int i = blockIdx.x * blockDim.x + threadIdx.x;
    if (i < n32) {
        float4 v = __ldg((const float4*)x + i);
        uint2 o;
        o.x = f2_to_bf2(v.x, v.y);
        o.y = f2_to_bf2(v.z, v.w);
        *((uint2*)xb + i) = o;
        return;
    }
    int j = i - n32;
    if (j < 128 * 256) {
        int nn = j >> 8, k = j & 255;
        float v = (k < 128) ? Wl1[k * 128 + nn] : Wr1[(k - 128) * 128 + nn];
        W1t[j] = __uint_as_float(f2tf32(v));
    } else if (j < 128 * 256 + 128 * 128) {
        int jj = j - 128 * 256;
        int nn = jj >> 7, k = jj & 127;
        float v = (nn < 64) ? Wl2[k * 64 + nn] : Wr2[k * 64 + (nn - 64)];
        W2t[jj] = __uint_as_float(f2tf32(v));
    }
}

// ---------------- wide gathers (range [base, nend)) ----------------
// gather128: half-warp per node. Row = 128 bf16 = 256B = 16 lanes x uint4.
__global__ void gather_mean128_w(const uint16_t* __restrict__ featb,
                                 const int* __restrict__ rowptr,
                                 const int* __restrict__ cnt,
                                 const int* __restrict__ eidx,
                                 float* __restrict__ mean, int base, int nend) {
    int gw   = (blockIdx.x * blockDim.x + threadIdx.x) >> 5;
    int lane = threadIdx.x & 31;
    int node = base + gw * 2 + (lane >> 4);
    int sl   = lane & 15;
    if (node >= nend) return;
    int beg = __ldg(&rowptr[node]);
    int deg = __ldg(&cnt[node]);
    int end = beg + deg;
    const uint4* fb = (const uint4*)featb;   // 16 uint4 per row
    float acc[8] = {0.f, 0.f, 0.f, 0.f, 0.f, 0.f, 0.f, 0.f};
    int j = beg;
    for (; j + 3 < end; j += 4) {
        int s0 = __ldg(&eidx[j]),     s1 = __ldg(&eidx[j + 1]);
        int s2 = __ldg(&eidx[j + 2]), s3 = __ldg(&eidx[j + 3]);
        uint4 v0 = __ldg(&fb[(size_t)s0 * 16 + sl]);
        uint4 v1 = __ldg(&fb[(size_t)s1 * 16 + sl]);
        uint4 v2 = __ldg(&fb[(size_t)s2 * 16 + sl]);
        uint4 v3 = __ldg(&fb[(size_t)s3 * 16 + sl]);
        acc_bf8(acc, v0); acc_bf8(acc, v1); acc_bf8(acc, v2); acc_bf8(acc, v3);
    }
    for (; j < end; ++j) {
        int s0 = __ldg(&eidx[j]);
        uint4 v0 = __ldg(&fb[(size_t)s0 * 16 + sl]);
        acc_bf8(acc, v0);
    }
    float inv = 1.0f / fmaxf((float)deg, 1.0f);
    float* mp = mean + (size_t)node * 128 + sl * 8;
    *(float4*)mp       = make_float4(acc[0] * inv, acc[1] * inv, acc[2] * inv, acc[3] * inv);
    *(float4*)(mp + 4) = make_float4(acc[4] * inv, acc[5] * inv, acc[6] * inv, acc[7] * inv);
}

// gather_final64: quarter-warp per node. Row = 64 bf16 = 128B = 8 lanes x uint4.
__global__ void gather_final64_w(const uint16_t* __restrict__ y2b,
                                 const float* __restrict__ y2hi,
                                 const float* __restrict__ bl2,
                                 const int* __restrict__ rowptr,
                                 const int* __restrict__ cnt,
                                 const int* __restrict__ eidx,
                                 float* __restrict__ out, int n) {
    int gw   = (blockIdx.x * blockDim.x + threadIdx.x) >> 5;
    int lane = threadIdx.x & 31;
    int node = gw * 4 + (lane >> 3);
    int sl   = lane & 7;
    if (node >= n) return;
    int beg = __ldg(&rowptr[node]);
    int deg = __ldg(&cnt[node]);
    int end = beg + deg;
    const uint4* fb = (const uint4*)y2b;     // 8 uint4 per row
    float acc[8] = {0.f, 0.f, 0.f, 0.f, 0.f, 0.f, 0.f, 0.f};
    int j = beg;
    for (; j + 3 < end; j += 4) {
        int s0 = __ldg(&eidx[j]),     s1 = __ldg(&eidx[j + 1]);
        int s2 = __ldg(&eidx[j + 2]), s3 = __ldg(&eidx[j + 3]);
        uint4 v0 = __ldg(&fb[(size_t)s0 * 8 + sl]);
        uint4 v1 = __ldg(&fb[(size_t)s1 * 8 + sl]);
        uint4 v2 = __ldg(&fb[(size_t)s2 * 8 + sl]);
        uint4 v3 = __ldg(&fb[(size_t)s3 * 8 + sl]);
        acc_bf8(acc, v0); acc_bf8(acc, v1); acc_bf8(acc, v2); acc_bf8(acc, v3);
    }
    for (; j < end; ++j) {
        int s0 = __ldg(&eidx[j]);
        uint4 v0 = __ldg(&fb[(size_t)s0 * 8 + sl]);
        acc_bf8(acc, v0);
    }
    float inv = 1.0f / fmaxf((float)deg, 1.0f);
    const float* yp = y2hi + (size_t)node * 64 + sl * 8;
    const float* bp = bl2 + sl * 8;
    float4 y0 = *(const float4*)yp, y1 = *(const float4*)(yp + 4);
    float4 b0 = *(const float4*)bp, b1 = *(const float4*)(bp + 4);
    float4 o0, o1;
    o0.x = 1.0f / (1.0f + __expf(-(acc[0] * inv + y0.x + b0.x)));
    o0.y = 1.0f / (1.0f + __expf(-(acc[1] * inv + y0.y + b0.y)));
    o0.z = 1.0f / (1.0f + __expf(-(acc[2] * inv + y0.z + b0.z)));
    o0.w = 1.0f / (1.0f + __expf(-(acc[3] * inv + y0.w + b0.w)));
    o1.x = 1.0f / (1.0f + __expf(-(acc[4] * inv + y1.x + b1.x)));
    o1.y = 1.0f / (1.0f + __expf(-(acc[5] * inv + y1.y + b1.y)));
    o1.z = 1.0f / (1.0f + __expf(-(acc[6] * inv + y1.z + b1.z)));
    o1.w = 1.0f / (1.0f + __expf(-(acc[7] * inv + y1.w + b1.w)));
    float* op = out + (size_t)node * 64 + sl * 8;
    *(float4*)op       = o0;
    *(float4*)(op + 4) = o1;
}

// ---------------------------------------------------------------------------
// TF32 mma.sync GEMM over rows [base, nend), cp.async double-buffered.
// C[128-tile,128] = A[*,KTOT] @ Wt^T (Wt: [128,KTOT] K-major, tf32-rounded).
// EPI 1: relu(c+bias) -> f32 out[n,128]
// EPI 2: cols<64 -> bf16 outb[n,64]; cols>=64 -> f32 outhi[n,64]
// ---------------------------------------------------------------------------
template<int KTOT, int HAS_A1, int EPI>
__global__ void __launch_bounds__(256, 2)
mma_gemm(const float* __restrict__ A0, const float* __restrict__ A1,
         const float* __restrict__ Wt, const float* __restrict__ bias,
         float* __restrict__ out, uint16_t* __restrict__ outb,
         float* __restrict__ outhi, int base, int nend)
{
    constexpr int NCHUNK = KTOT / 32;
    extern __shared__ float smem[];
    const uint32_t* As = (const uint32_t*)smem;           // [2][4096]
    const uint32_t* Ws = (const uint32_t*)(smem + 8192);  // [2][4096]

    const int tid  = threadIdx.x;
    const int wid  = tid >> 5;
    const int lane = tid & 31;
    const int wm   = wid & 1;
    const int wn   = wid >> 1;
    const int g    = lane >> 2;
    const int tg   = lane & 3;
    const int row0 = base + blockIdx.x * 128;

    const uint32_t as_b = smem_u32(smem);
    const uint32_t ws_b = as_b + 8192 * 4;

    float c[4][4][4];
#pragma unroll
    for (int mi = 0; mi < 4; mi++)
#pragma unroll
        for (int ni = 0; ni < 4; ni++)
#pragma unroll
            for (int j = 0; j < 4; j++) c[mi][ni][j] = 0.f;

    auto prefetch = [&](int ch, int stage) {
        const int kcol = ch * 32;
        const float* Asrc = A0;
        int kk = kcol;
        if (HAS_A1 && kcol >= 128) { Asrc = A1; kk = kcol - 128; }
        const uint32_t sofs = (uint32_t)stage << 14;
#pragma unroll
        for (int i = tid; i < 1024; i += 256) {
            int r = i >> 3, k4 = i & 7;
            uint32_t widx = (uint32_t)((r << 5) + ((k4 << 2) ^ ((r & 7) << 2)));
            int node = row0 + r;
            int ok = (node < nend);
            const float* gA = Asrc + (size_t)(ok ? node : 0) * 128 + kk + (k4 << 2);
            cp_async16(as_b + sofs + widx * 4, gA, ok ? 16 : 0);
            const float* gW = Wt + (size_t)r * KTOT + kcol + (k4 << 2);
            cp_async16(ws_b + sofs + widx * 4, gW, 16);
        }
        CP_COMMIT();
    };

    prefetch(0, 0);

#pragma unroll 1
    for (int ch = 0; ch < NCHUNK; ++ch) {
        const int stage = ch & 1;
        if (ch + 1 < NCHUNK) {
            prefetch(ch + 1, stage ^ 1);
            CP_WAIT1();
        } else {
            CP_WAIT0();
        }
        __syncthreads();

        const uint32_t* Ab = As + (stage << 12);
        const uint32_t* Wb = Ws + (stage << 12);

#pragma unroll
        for (int ks = 0; ks < 4; ++ks) {
            const int k0 = ks * 8;
            uint32_t a[4][4];
#pragma unroll
            for (int mi = 0; mi < 4; mi++) {
                int r0 = wm * 64 + mi * 16 + g;
                a[mi][0] = Ab[swz(r0,     k0 + tg)];
                a[mi][1] = Ab[swz(r0 + 8, k0 + tg)];
                a[mi][2] = Ab[swz(r0,     k0 + tg + 4)];
                a[mi][3] = Ab[swz(r0 + 8, k0 + tg + 4)];
            }
#pragma unroll
            for (int ni = 0; ni < 4; ni++) {
                int nb = wn * 32 + ni * 8 + g;
                uint32_t b[2];
                b[0] = Wb[swz(nb, k0 + tg)];
                b[1] = Wb[swz(nb, k0 + tg + 4)];
#pragma unroll
                for (int mi = 0; mi < 4; mi++)
                    mma_tf32(c[mi][ni], a[mi], b);
            }
        }
        __syncthreads();
    }

#pragma unroll
    for (int mi = 0; mi < 4; mi++) {
#pragma unroll
        for (int half = 0; half < 2; half++) {
            int row = row0 + wm * 64 + mi * 16 + g + half * 8;
            if (row < nend) {
#pragma unroll
                for (int ni = 0; ni < 4; ni++) {
                    int col = wn * 32 + ni * 8 + tg * 2;
                    float v0 = c[mi][ni][half * 2 + 0];
                    float v1 = c[mi][ni][half * 2 + 1];
                    if (EPI == 1) {
                        v0 = fmaxf(v0 + __ldg(&bias[col]), 0.f);
                        v1 = fmaxf(v1 + __ldg(&bias[col + 1]), 0.f);
                        *(float2*)(out + (size_t)row * 128 + col) = make_float2(v0, v1);
                    } else {
                        if (col < 64) {
                            *(uint32_t*)(outb + (size_t)row * 64 + col) = f2_to_bf2(v0, v1);
                        } else {
                            *(float2*)(outhi + (size_t)row * 64 + (col - 64)) =
                                make_float2(v0, v1);
                        }
                    }
                }
            }
        }
    }
}

// ---------------------------------------------------------------------------
extern "C" void kernel_launch(void* const* d_in, const int* in_sizes, int n_in,
                              void* d_out, int out_size) {
    const float* x   = (const float*)d_in[0];
    const void*  ei  = d_in[1];
    const float* Wl1 = (const float*)d_in[2];
    const float* bl1 = (const float*)d_in[3];
    const float* Wr1 = (const float*)d_in[4];
    const float* Wl2 = (const float*)d_in[5];
    const float* bl2 = (const float*)d_in[6];
    const float* Wr2 = (const float*)d_in[7];
    float* out = (float*)d_out;

    const int n  = in_sizes[0] / 128;   // 100000
    const int ne = in_sizes[1] / 2;     // 1600000

    float *mean, *h, *y2hi, *w1t, *w2t;
    uint16_t *xb, *y2b;
    int *cnt, *cur, *rowptr, *eidx, *total;
    cudaGetSymbolAddress((void**)&mean,   g_mean);
    cudaGetSymbolAddress((void**)&h,      g_h);
    cudaGetSymbolAddress((void**)&y2hi,   g_y2hi);
    cudaGetSymbolAddress((void**)&xb,     g_xb);
    cudaGetSymbolAddress((void**)&y2b,    g_y2b);
    cudaGetSymbolAddress((void**)&w1t,    g_w1t);
    cudaGetSymbolAddress((void**)&w2t,    g_w2t);
    cudaGetSymbolAddress((void**)&cnt,    g_cnt);
    cudaGetSymbolAddress((void**)&cur,    g_cur);
    cudaGetSymbolAddress((void**)&rowptr, g_rowptr);
    cudaGetSymbolAddress((void**)&eidx,   g_eidx);
    cudaGetSymbolAddress((void**)&total,  g_total);

    cudaFuncSetAttribute(mma_gemm<256, 1, 1>,
                         cudaFuncAttributeMaxDynamicSharedMemorySize, 65536);
    cudaFuncSetAttribute(mma_gemm<128, 0, 2>,
                         cudaFuncAttributeMaxDynamicSharedMemorySize, 65536);

    // split point (multiple of 128)
    const int n2    = ((n / 2 + 127) / 128) * 128;   // 50048
    const int nscan = (n + 511) / 512;
    const int eblk2 = (ne / 2 + 255) / 256 + 1;
    const int gblkA = (n2 + 15) / 16;
    const int gblkB = (n - n2 + 15) / 16;
    const int gblkF = (n + 31) / 32;
    const int mblkA = n2 / 128;
    const int mblkB = (n - n2 + 127) / 128;
    const int n32   = n * 32;
    const int pitems = n32 + 128 * 256 + 128 * 128;
    const int pblk  = (pitems + 255) / 256;

    // Fork resources (host-side only; intentionally not destroyed — capture-
    // referenced objects must outlive the graph).
    cudaStream_t sB;
    cudaStreamCreateWithFlags(&sB, cudaStreamNonBlocking);
    cudaEvent_t ev0, evP, evGA, ev2A;
    cudaEventCreateWithFlags(&ev0,  cudaEventDisableTiming);
    cudaEventCreateWithFlags(&evP,  cudaEventDisableTiming);
    cudaEventCreateWithFlags(&evGA, cudaEventDisableTiming);
    cudaEventCreateWithFlags(&ev2A, cudaEventDisableTiming);

    // ---- S0: zero cnt + detect; fork prep on S1 ----
    zero_detect_kernel<<<(n + 255) / 256, 256>>>(cnt, (const int*)ei, n);
    cudaEventRecord(ev0, 0);
    cudaStreamWaitEvent(sB, ev0, 0);
    prep_kernel<<<pblk, 256, 0, sB>>>(x, xb, Wl1, Wr1, w1t, Wl2, Wr2, w2t, n32);
    cudaEventRecord(evP, sB);

    // ---- S0: CSR build ----
    hist_kernel<<<eblk2, 256>>>(ei, cnt, ne);
    scan_kernel<<<nscan, 512>>>(cnt, rowptr, cur, total, n);
    fill_kernel<<<eblk2, 256>>>(ei, cur, eidx, ne);

    // ---- S0: gather half A, then half B ----
    cudaStreamWaitEvent(0, evP, 0);
    gather_mean128_w<<<gblkA, 256>>>(xb, rowptr, cnt, eidx, mean, 0, n2);
    cudaEventRecord(evGA, 0);
    gather_mean128_w<<<gblkB, 256>>>(xb, rowptr, cnt, eidx, mean, n2, n);

    // ---- S1: layer-1 + layer-2 GEMMs for half A (overlaps gather_B) ----
    cudaStreamWaitEvent(sB, evGA, 0);
    mma_gemm<256, 1, 1><<<mblkA, 256, 65536, sB>>>(mean, x, w1t, bl1, h,
                                                   nullptr, nullptr, 0, n2);
    mma_gemm<128, 0, 2><<<mblkA, 256, 65536, sB>>>(h, nullptr, w2t, nullptr,
                                                   nullptr, y2b, y2hi, 0, n2);
    cudaEventRecord(ev2A, sB);

    // ---- S0: GEMMs for half B ----
    mma_gemm<256, 1, 1><<<mblkB, 256, 65536>>>(mean, x, w1t, bl1, h,
                                               nullptr, nullptr, n2, n);
    mma_gemm<128, 0, 2><<<mblkB, 256, 65536>>>(h, nullptr, w2t, nullptr,
                                               nullptr, y2b, y2hi, n2, n);

    // ---- S0: join + final gather ----
    cudaStreamWaitEvent(0, ev2A, 0);
    gather_final64_w<<<gblkF, 256>>>(y2b, y2hi, bl2, rowptr, cnt, eidx, out, n);
}

// round 11
// speedup vs baseline: 1.4419x; 1.2071x over previous
#include <cuda_runtime.h>
#include <cuda_fp16.h>
#include <cstdint>
#include <math.h>

// ---------------------------------------------------------------------------
// GraphSAGE 2-layer, all-fp16 intermediates (10-bit mantissa ≈ tf32), f32 accum.
// CSR gather-mean (fp16 payload, 16B-lane loads) + fp16 mma.m16n8k16 GEMMs
// (cp.async double-buffered, pad-20-word SMEM). Split-half GEMM/gather overlap.
// ---------------------------------------------------------------------------

#define N_MAX 100000
#define E_MAX 1600000

__device__ uint32_t g_meanw[(size_t)N_MAX * 64];   // mean1, fp16 pairs
__device__ uint32_t g_xhw  [(size_t)N_MAX * 64];   // fp16(x) pairs
__device__ uint32_t g_hw   [(size_t)N_MAX * 64];   // h, fp16 pairs
__device__ uint32_t g_y2bw [(size_t)N_MAX * 32];   // y2 lo cols, fp16 pairs
__device__ float    g_y2hi [(size_t)N_MAX * 64];   // y2 hi cols, f32
__device__ uint32_t g_w1tw [128 * 128];            // [N=128][K=256] fp16 pairs
__device__ uint32_t g_w2tw [128 * 64];             // [N=128][K=128] fp16 pairs
__device__ int      g_cnt[N_MAX];
__device__ int      g_cur[N_MAX];
__device__ int      g_rowptr[N_MAX];
__device__ int      g_eidx[E_MAX];
__device__ int      g_total;
__device__ int      g_is64;

// ---------------- helpers ----------------
__device__ __forceinline__ float2 h2f2(uint32_t v) {
    __half2 h = *reinterpret_cast<__half2*>(&v);
    return __half22float2(h);
}
__device__ __forceinline__ uint32_t f2h2(float lo, float hi) {
    __half2 h = __floats2half2_rn(lo, hi);
    return *reinterpret_cast<uint32_t*>(&h);
}
__device__ __forceinline__ void mma_f16(float (&c)[4], const uint32_t (&a)[4],
                                        const uint32_t (&b)[2]) {
    asm volatile(
        "mma.sync.aligned.m16n8k16.row.col.f32.f16.f16.f32 "
        "{%0,%1,%2,%3}, {%4,%5,%6,%7}, {%8,%9}, {%0,%1,%2,%3};"
        : "+f"(c[0]), "+f"(c[1]), "+f"(c[2]), "+f"(c[3])
        : "r"(a[0]), "r"(a[1]), "r"(a[2]), "r"(a[3]), "r"(b[0]), "r"(b[1]));
}
__device__ __forceinline__ void acc_h8(float (&acc)[8], uint4 v) {
    float2 f0 = h2f2(v.x), f1 = h2f2(v.y);
    float2 f2 = h2f2(v.z), f3 = h2f2(v.w);
    acc[0] += f0.x; acc[1] += f0.y; acc[2] += f1.x; acc[3] += f1.y;
    acc[4] += f2.x; acc[5] += f2.y; acc[6] += f3.x; acc[7] += f3.y;
}
__device__ __forceinline__ uint32_t smem_u32(const void* p) {
    uint32_t a;
    asm("{ .reg .u64 t; cvta.to.shared.u64 t, %1; cvt.u32.u64 %0, t; }"
        : "=r"(a) : "l"(p));
    return a;
}
__device__ __forceinline__ void cp_async16(uint32_t smem, const void* g, int src_bytes) {
    asm volatile("cp.async.ca.shared.global [%0], [%1], 16, %2;"
                 :: "r"(smem), "l"(g), "r"(src_bytes) : "memory");
}
#define CP_COMMIT() asm volatile("cp.async.commit_group;" ::: "memory")
#define CP_WAIT0()  asm volatile("cp.async.wait_group 0;" ::: "memory")
#define CP_WAIT1()  asm volatile("cp.async.wait_group 1;" ::: "memory")

// ---------------- CSR build ----------------
__device__ __forceinline__ int edge_at(const void* ei, long long idx, int is64) {
    if (is64) return (int)((const long long*)ei)[idx];
    return ((const int*)ei)[idx];
}
__global__ void zero_detect_kernel(int* __restrict__ cnt, const int* __restrict__ ei, int n) {
    int i = blockIdx.x * blockDim.x + threadIdx.x;
    if (i < n) cnt[i] = 0;
    if (i == 0) {
        int nz = 0;
        for (int q = 1; q < 256; q += 2) nz += (ei[q] != 0);
        g_is64 = (nz == 0) ? 1 : 0;
        g_total = 0;
    }
}
__global__ void hist_kernel(const void* __restrict__ ei, int* __restrict__ cnt, int ne) {
    int i = blockIdx.x * blockDim.x + threadIdx.x;
    int is64 = g_is64;
    int i2 = i * 2;
    if (((ne & 1) == 0) && i2 + 1 < ne) {
        int d0, d1;
        if (is64) {
            longlong2 v = __ldg((const longlong2*)ei + (ne + i2) / 2);
            d0 = (int)v.x; d1 = (int)v.y;
        } else {
            int2 v = __ldg((const int2*)ei + (ne + i2) / 2);
            d0 = v.x; d1 = v.y;
        }
        atomicAdd(&cnt[d0], 1);
        atomicAdd(&cnt[d1], 1);
    } else {
        for (int q = 0; q < 2; q++)
            if (i2 + q < ne)
                atomicAdd(&cnt[edge_at(ei, (long long)ne + i2 + q, is64)], 1);
    }
}
__global__ void scan_kernel(const int* __restrict__ cnt, int* __restrict__ rowptr,
                            int* __restrict__ cur, int* __restrict__ total, int n) {
    __shared__ int wsum[16];
    __shared__ int base_s;
    int tid = threadIdx.x;                 // 512
    int i = blockIdx.x * 512 + tid;
    int v = (i < n) ? cnt[i] : 0;
    int lane = tid & 31, w = tid >> 5;
    int p = v;
#pragma unroll
    for (int off = 1; off < 32; off <<= 1) {
        int t = __shfl_up_sync(0xFFFFFFFFu, p, off);
        if (lane >= off) p += t;
    }
    if (lane == 31) wsum[w] = p;
    __syncthreads();
    if (w == 0) {
        int s = (lane < 16) ? wsum[lane] : 0;
#pragma unroll
        for (int off = 1; off < 16; off <<= 1) {
            int t = __shfl_up_sync(0xFFFFFFFFu, s, off);
            if (lane >= off) s += t;
        }
        if (lane < 16) wsum[lane] = s;
        if (lane == 15) base_s = atomicAdd(total, s);
    }
    __syncthreads();
    int woff = (w > 0) ? wsum[w - 1] : 0;
    int excl = base_s + woff + p - v;
    if (i < n) { rowptr[i] = excl; cur[i] = excl; }
}
__global__ void fill_kernel(const void* __restrict__ ei, int* __restrict__ cur,
                            int* __restrict__ eidx, int ne) {
    int i = blockIdx.x * blockDim.x + threadIdx.x;
    int is64 = g_is64;
    int i2 = i * 2;
    if (((ne & 1) == 0) && i2 + 1 < ne) {
        int s0, s1, d0, d1;
        if (is64) {
            longlong2 sv = __ldg((const longlong2*)ei + i2 / 2);
            longlong2 dv = __ldg((const longlong2*)ei + (ne + i2) / 2);
            s0 = (int)sv.x; s1 = (int)sv.y;
            d0 = (int)dv.x; d1 = (int)dv.y;
        } else {
            int2 sv = __ldg((const int2*)ei + i2 / 2);
            int2 dv = __ldg((const int2*)ei + (ne + i2) / 2);
            s0 = sv.x; s1 = sv.y;
            d0 = dv.x; d1 = dv.y;
        }
        eidx[atomicAdd(&cur[d0], 1)] = s0;
        eidx[atomicAdd(&cur[d1], 1)] = s1;
    } else {
        for (int q = 0; q < 2; q++)
            if (i2 + q < ne) {
                int s = edge_at(ei, i2 + q, is64);
                int d = edge_at(ei, (long long)ne + i2 + q, is64);
                eidx[atomicAdd(&cur[d], 1)] = s;
            }
    }
}

// ---------------- prep: x->fp16, W transposes (fp16 pairs) ----------------
__global__ void prep_kernel(const float* __restrict__ x, uint32_t* __restrict__ xhw,
                            const float* __restrict__ Wl1, const float* __restrict__ Wr1,
                            uint32_t* __restrict__ W1tw,
                            const float* __restrict__ Wl2, const float* __restrict__ Wr2,
                            uint32_t* __restrict__ W2tw, int n32) {
    int i = blockIdx.x * blockDim.x + threadIdx.x;
    if (i < n32) {
        float4 v = __ldg((const float4*)x + i);
        uint2 o;
        o.x = f2h2(v.x, v.y);
        o.y = f2h2(v.z, v.w);
        *((uint2*)xhw + i) = o;
        return;
    }
    int j = i - n32;
    if (j < 128 * 128) {                       // W1tw: [nn][w], k = 2w,2w+1 over 256
        int nn = j >> 7, w = j & 127;
        int k0 = 2 * w;
        float v0, v1;
        if (k0 < 128) { v0 = Wl1[k0 * 128 + nn]; v1 = Wl1[(k0 + 1) * 128 + nn]; }
        else          { v0 = Wr1[(k0 - 128) * 128 + nn]; v1 = Wr1[(k0 - 127) * 128 + nn]; }
        W1tw[j] = f2h2(v0, v1);
    } else if (j < 128 * 128 + 128 * 64) {     // W2tw: [nn][w], k = 2w,2w+1 over 128
        int jj = j - 128 * 128;
        int nn = jj >> 6, w = jj & 63;
        int k0 = 2 * w;
        float v0, v1;
        if (nn < 64) { v0 = Wl2[k0 * 64 + nn];        v1 = Wl2[(k0 + 1) * 64 + nn]; }
        else         { v0 = Wr2[k0 * 64 + (nn - 64)]; v1 = Wr2[(k0 + 1) * 64 + (nn - 64)]; }
        W2tw[jj] = f2h2(v0, v1);
    }
}

// ---------------- wide gathers (range [base, nend)) ----------------
// gather128: half-warp per node. Row = 64 words = 16 uint4 (256B).
__global__ void gather_mean128_w(const uint32_t* __restrict__ featw,
                                 const int* __restrict__ rowptr,
                                 const int* __restrict__ cnt,
                                 const int* __restrict__ eidx,
                                 uint32_t* __restrict__ meanw, int base, int nend) {
    int gw   = (blockIdx.x * blockDim.x + threadIdx.x) >> 5;
    int lane = threadIdx.x & 31;
    int node = base + gw * 2 + (lane >> 4);
    int sl   = lane & 15;
    if (node >= nend) return;
    int beg = __ldg(&rowptr[node]);
    int deg = __ldg(&cnt[node]);
    int end = beg + deg;
    const uint4* fb = (const uint4*)featw;   // 16 uint4 per row
    float acc[8] = {0.f, 0.f, 0.f, 0.f, 0.f, 0.f, 0.f, 0.f};
    int j = beg;
    for (; j + 3 < end; j += 4) {
        int s0 = __ldg(&eidx[j]),     s1 = __ldg(&eidx[j + 1]);
        int s2 = __ldg(&eidx[j + 2]), s3 = __ldg(&eidx[j + 3]);
        uint4 v0 = __ldg(&fb[(size_t)s0 * 16 + sl]);
        uint4 v1 = __ldg(&fb[(size_t)s1 * 16 + sl]);
        uint4 v2 = __ldg(&fb[(size_t)s2 * 16 + sl]);
        uint4 v3 = __ldg(&fb[(size_t)s3 * 16 + sl]);
        acc_h8(acc, v0); acc_h8(acc, v1); acc_h8(acc, v2); acc_h8(acc, v3);
    }
    for (; j < end; ++j) {
        int s0 = __ldg(&eidx[j]);
        uint4 v0 = __ldg(&fb[(size_t)s0 * 16 + sl]);
        acc_h8(acc, v0);
    }
    float inv = 1.0f / fmaxf((float)deg, 1.0f);
    uint4 o;
    o.x = f2h2(acc[0] * inv, acc[1] * inv);
    o.y = f2h2(acc[2] * inv, acc[3] * inv);
    o.z = f2h2(acc[4] * inv, acc[5] * inv);
    o.w = f2h2(acc[6] * inv, acc[7] * inv);
    *(uint4*)(meanw + (size_t)node * 64 + sl * 4) = o;
}

// gather_final64: quarter-warp per node. Row = 32 words = 8 uint4 (128B).
__global__ void gather_final64_w(const uint32_t* __restrict__ y2bw,
                                 const float* __restrict__ y2hi,
                                 const float* __restrict__ bl2,
                                 const int* __restrict__ rowptr,
                                 const int* __restrict__ cnt,
                                 const int* __restrict__ eidx,
                                 float* __restrict__ out, int n) {
    int gw   = (blockIdx.x * blockDim.x + threadIdx.x) >> 5;
    int lane = threadIdx.x & 31;
    int node = gw * 4 + (lane >> 3);
    int sl   = lane & 7;
    if (node >= n) return;
    int beg = __ldg(&rowptr[node]);
    int deg = __ldg(&cnt[node]);
    int end = beg + deg;
    const uint4* fb = (const uint4*)y2bw;    // 8 uint4 per row
    float acc[8] = {0.f, 0.f, 0.f, 0.f, 0.f, 0.f, 0.f, 0.f};
    int j = beg;
    for (; j + 3 < end; j += 4) {
        int s0 = __ldg(&eidx[j]),     s1 = __ldg(&eidx[j + 1]);
        int s2 = __ldg(&eidx[j + 2]), s3 = __ldg(&eidx[j + 3]);
        uint4 v0 = __ldg(&fb[(size_t)s0 * 8 + sl]);
        uint4 v1 = __ldg(&fb[(size_t)s1 * 8 + sl]);
        uint4 v2 = __ldg(&fb[(size_t)s2 * 8 + sl]);
        uint4 v3 = __ldg(&fb[(size_t)s3 * 8 + sl]);
        acc_h8(acc, v0); acc_h8(acc, v1); acc_h8(acc, v2); acc_h8(acc, v3);
    }
    for (; j < end; ++j) {
        int s0 = __ldg(&eidx[j]);
        uint4 v0 = __ldg(&fb[(size_t)s0 * 8 + sl]);
        acc_h8(acc, v0);
    }
    float inv = 1.0f / fmaxf((float)deg, 1.0f);
    const float* yp = y2hi + (size_t)node * 64 + sl * 8;
    const float* bp = bl2 + sl * 8;
    float4 y0 = *(const float4*)yp, y1 = *(const float4*)(yp + 4);
    float4 b0 = *(const float4*)bp, b1 = *(const float4*)(bp + 4);
    float4 o0, o1;
    o0.x = 1.0f / (1.0f + __expf(-(acc[0] * inv + y0.x + b0.x)));
    o0.y = 1.0f / (1.0f + __expf(-(acc[1] * inv + y0.y + b0.y)));
    o0.z = 1.0f / (1.0f + __expf(-(acc[2] * inv + y0.z + b0.z)));
    o0.w = 1.0f / (1.0f + __expf(-(acc[3] * inv + y0.w + b0.w)));
    o1.x = 1.0f / (1.0f + __expf(-(acc[4] * inv + y1.x + b1.x)));
    o1.y = 1.0f / (1.0f + __expf(-(acc[5] * inv + y1.y + b1.y)));
    o1.z = 1.0f / (1.0f + __expf(-(acc[6] * inv + y1.z + b1.z)));
    o1.w = 1.0f / (1.0f + __expf(-(acc[7] * inv + y1.w + b1.w)));
    float* op = out + (size_t)node * 64 + sl * 8;
    *(float4*)op       = o0;
    *(float4*)(op + 4) = o1;
}

// ---------------------------------------------------------------------------
// fp16 mma.m16n8k16 GEMM over rows [base, nend), cp.async double-buffered.
// A, W stored as fp16 pairs (u32 words). KW = K/2 words (64 or 128).
// SMEM tile: [128 rows][16 words] padded to 20 words/row (conflict-free).
// EPI 1: relu(c+bias) -> fp16 outw[n,64w]
// EPI 2: cols<64 -> fp16 outbw[n,32w]; cols>=64 -> f32 outhi[n,64]
// ---------------------------------------------------------------------------
template<int KW, int HAS_A1, int EPI>
__global__ void __launch_bounds__(256, 2)
mma_gemm(const uint32_t* __restrict__ A0w, const uint32_t* __restrict__ A1w,
         const uint32_t* __restrict__ Wtw, const float* __restrict__ bias,
         uint32_t* __restrict__ outw, uint32_t* __restrict__ outbw,
         float* __restrict__ outhi, int base, int nend)
{
    constexpr int NCHUNK = KW / 16;              // 16 words = 32 k per chunk
    constexpr int TILE_W = 2560;                 // 128 rows * 20 words
    extern __shared__ uint32_t smem[];           // [4][2560]: A0,A1,W0,W1

    const int tid  = threadIdx.x;
    const int wid  = tid >> 5;
    const int lane = tid & 31;
    const int wm   = wid & 1;
    const int wn   = wid >> 1;
    const int g    = lane >> 2;
    const int tg   = lane & 3;
    const int row0 = base + blockIdx.x * 128;

    const uint32_t sm_b = smem_u32(smem);

    float c[4][4][4];
#pragma unroll
    for (int mi = 0; mi < 4; mi++)
#pragma unroll
        for (int ni = 0; ni < 4; ni++)
#pragma unroll
            for (int j = 0; j < 4; j++) c[mi][ni][j] = 0.f;

    auto prefetch = [&](int ch, int stage) {
        const uint32_t* Aw = A0w;
        int kkw = ch * 16;
        if (HAS_A1 && ch >= NCHUNK / 2) { Aw = A1w; kkw = (ch - NCHUNK / 2) * 16; }
#pragma unroll
        for (int i = tid; i < 512; i += 256) {
            int r = i >> 2, g4 = (i & 3) << 2;
            int node = row0 + r;
            int ok = (node < nend);
            const uint32_t* gA = Aw + (size_t)(ok ? node : 0) * 64 + kkw + g4;
            cp_async16(sm_b + (uint32_t)((stage * TILE_W + r * 20 + g4) * 4), gA, ok ? 16 : 0);
            const uint32_t* gW = Wtw + (size_t)r * KW + ch * 16 + g4;
            cp_async16(sm_b + (uint32_t)(((2 + stage) * TILE_W + r * 20 + g4) * 4), gW, 16);
        }
        CP_COMMIT();
    };

    prefetch(0, 0);

#pragma unroll 1
    for (int ch = 0; ch < NCHUNK; ++ch) {
        const int stage = ch & 1;
        if (ch + 1 < NCHUNK) {
            prefetch(ch + 1, stage ^ 1);
            CP_WAIT1();
        } else {
            CP_WAIT0();
        }
        __syncthreads();

        const uint32_t* Ab = smem + stage * TILE_W;
        const uint32_t* Wb = smem + (2 + stage) * TILE_W;

#pragma unroll
        for (int ks = 0; ks < 2; ++ks) {
            const int k0 = ks * 8;
            uint32_t a[4][4];
#pragma unroll
            for (int mi = 0; mi < 4; mi++) {
                int r0 = wm * 64 + mi * 16 + g;
                a[mi][0] = Ab[r0 * 20 + k0 + tg];
                a[mi][1] = Ab[(r0 + 8) * 20 + k0 + tg];
                a[mi][2] = Ab[r0 * 20 + k0 + tg + 4];
                a[mi][3] = Ab[(r0 + 8) * 20 + k0 + tg + 4];
            }
#pragma unroll
            for (int ni = 0; ni < 4; ni++) {
                int nb = wn * 32 + ni * 8 + g;
                uint32_t b[2];
                b[0] = Wb[nb * 20 + k0 + tg];
                b[1] = Wb[nb * 20 + k0 + tg + 4];
#pragma unroll
                for (int mi = 0; mi < 4; mi++)
                    mma_f16(c[mi][ni], a[mi], b);
            }
        }
        __syncthreads();
    }

#pragma unroll
    for (int mi = 0; mi < 4; mi++) {
#pragma unroll
        for (int half = 0; half < 2; half++) {
            int row = row0 + wm * 64 + mi * 16 + g + half * 8;
            if (row < nend) {
#pragma unroll
                for (int ni = 0; ni < 4; ni++) {
                    int col = wn * 32 + ni * 8 + tg * 2;
                    float v0 = c[mi][ni][half * 2 + 0];
                    float v1 = c[mi][ni][half * 2 + 1];
                    if (EPI == 1) {
                        v0 = fmaxf(v0 + __ldg(&bias[col]), 0.f);
                        v1 = fmaxf(v1 + __ldg(&bias[col + 1]), 0.f);
                        outw[(size_t)row * 64 + (col >> 1)] = f2h2(v0, v1);
                    } else {
                        if (col < 64) {
                            outbw[(size_t)row * 32 + (col >> 1)] = f2h2(v0, v1);
                        } else {
                            *(float2*)(outhi + (size_t)row * 64 + (col - 64)) =
                                make_float2(v0, v1);
                        }
                    }
                }
            }
        }
    }
}

// ---------------------------------------------------------------------------
extern "C" void kernel_launch(void* const* d_in, const int* in_sizes, int n_in,
                              void* d_out, int out_size) {
    const float* x   = (const float*)d_in[0];
    const void*  ei  = d_in[1];
    const float* Wl1 = (const float*)d_in[2];
    const float* bl1 = (const float*)d_in[3];
    const float* Wr1 = (const float*)d_in[4];
    const float* Wl2 = (const float*)d_in[5];
    const float* bl2 = (const float*)d_in[6];
    const float* Wr2 = (const float*)d_in[7];
    float* out = (float*)d_out;

    const int n  = in_sizes[0] / 128;   // 100000
    const int ne = in_sizes[1] / 2;     // 1600000

    uint32_t *meanw, *xhw, *hw, *y2bw, *w1tw, *w2tw;
    float *y2hi;
    int *cnt, *cur, *rowptr, *eidx, *total;
    cudaGetSymbolAddress((void**)&meanw,  g_meanw);
    cudaGetSymbolAddress((void**)&xhw,    g_xhw);
    cudaGetSymbolAddress((void**)&hw,     g_hw);
    cudaGetSymbolAddress((void**)&y2bw,   g_y2bw);
    cudaGetSymbolAddress((void**)&y2hi,   g_y2hi);
    cudaGetSymbolAddress((void**)&w1tw,   g_w1tw);
    cudaGetSymbolAddress((void**)&w2tw,   g_w2tw);
    cudaGetSymbolAddress((void**)&cnt,    g_cnt);
    cudaGetSymbolAddress((void**)&cur,    g_cur);
    cudaGetSymbolAddress((void**)&rowptr, g_rowptr);
    cudaGetSymbolAddress((void**)&eidx,   g_eidx);
    cudaGetSymbolAddress((void**)&total,  g_total);

    const int SMEM_BYTES = 4 * 2560 * 4;   // 40KB
    cudaFuncSetAttribute(mma_gemm<128, 1, 1>,
                         cudaFuncAttributeMaxDynamicSharedMemorySize, SMEM_BYTES);
    cudaFuncSetAttribute(mma_gemm<64, 0, 2>,
                         cudaFuncAttributeMaxDynamicSharedMemorySize, SMEM_BYTES);

    const int n2    = ((n / 2 + 127) / 128) * 128;   // split point
    const int nscan = (n + 511) / 512;
    const int eblk2 = (ne / 2 + 255) / 256 + 1;
    const int gblkA = (n2 + 15) / 16;
    const int gblkB = (n - n2 + 15) / 16;
    const int gblkF = (n + 31) / 32;
    const int mblkA = n2 / 128;
    const int mblkB = (n - n2 + 127) / 128;
    const int n32   = n * 32;
    const int pitems = n32 + 128 * 128 + 128 * 64;
    const int pblk  = (pitems + 255) / 256;

    // Fork resources (host-side only; intentionally not destroyed — capture-
    // referenced objects must outlive the graph).
    cudaStream_t sB;
    cudaStreamCreateWithFlags(&sB, cudaStreamNonBlocking);
    cudaEvent_t ev0, evP, evGA, ev2A;
    cudaEventCreateWithFlags(&ev0,  cudaEventDisableTiming);
    cudaEventCreateWithFlags(&evP,  cudaEventDisableTiming);
    cudaEventCreateWithFlags(&evGA, cudaEventDisableTiming);
    cudaEventCreateWithFlags(&ev2A, cudaEventDisableTiming);

    // ---- S0: zero cnt + detect; fork prep on S1 ----
    zero_detect_kernel<<<(n + 255) / 256, 256>>>(cnt, (const int*)ei, n);
    cudaEventRecord(ev0, 0);
    cudaStreamWaitEvent(sB, ev0, 0);
    prep_kernel<<<pblk, 256, 0, sB>>>(x, xhw, Wl1, Wr1, w1tw, Wl2, Wr2, w2tw, n32);
    cudaEventRecord(evP, sB);

    // ---- S0: CSR build ----
    hist_kernel<<<eblk2, 256>>>(ei, cnt, ne);
    scan_kernel<<<nscan, 512>>>(cnt, rowptr, cur, total, n);
    fill_kernel<<<eblk2, 256>>>(ei, cur, eidx, ne);

    // ---- S0: gather half A, then half B ----
    cudaStreamWaitEvent(0, evP, 0);
    gather_mean128_w<<<gblkA, 256>>>(xhw, rowptr, cnt, eidx, meanw, 0, n2);
    cudaEventRecord(evGA, 0);
    gather_mean128_w<<<gblkB, 256>>>(xhw, rowptr, cnt, eidx, meanw, n2, n);

    // ---- S1: layer-1 + layer-2 GEMMs for half A (overlaps gather_B) ----
    cudaStreamWaitEvent(sB, evGA, 0);
    mma_gemm<128, 1, 1><<<mblkA, 256, SMEM_BYTES, sB>>>(meanw, xhw, w1tw, bl1,
                                                        hw, nullptr, nullptr, 0, n2);
    mma_gemm<64, 0, 2><<<mblkA, 256, SMEM_BYTES, sB>>>(hw, nullptr, w2tw, nullptr,
                                                       nullptr, y2bw, y2hi, 0, n2);
    cudaEventRecord(ev2A, sB);

    // ---- S0: GEMMs for half B ----
    mma_gemm<128, 1, 1><<<mblkB, 256, SMEM_BYTES>>>(meanw, xhw, w1tw, bl1,
                                                    hw, nullptr, nullptr, n2, n);
    mma_gemm<64, 0, 2><<<mblkB, 256, SMEM_BYTES>>>(hw, nullptr, w2tw, nullptr,
                                                   nullptr, y2bw, y2hi, n2, n);

    // ---- S0: join + final gather ----
    cudaStreamWaitEvent(0, ev2A, 0);
    gather_final64_w<<<gblkF, 256>>>(y2bw, y2hi, bl2, rowptr, cnt, eidx, out, n);
}